// round 2
// baseline (speedup 1.0000x reference)
#include <cuda_runtime.h>
#include <math.h>

#define NB 8
#define NT 512
#define NH 256
#define NM 4096
#define NW 256

typedef unsigned long long ull;

#define FMA2(d,a,b,c) asm("fma.rn.f32x2 %0,%1,%2,%3;" : "=l"(d) : "l"(a), "l"(b), "l"(c))
#define MUL2(d,a,b)   asm("mul.rn.f32x2 %0,%1,%2;"    : "=l"(d) : "l"(a), "l"(b))
#define ADD2(d,a,b)   asm("add.rn.f32x2 %0,%1,%2;"    : "=l"(d) : "l"(a), "l"(b))

__device__ __forceinline__ ull pk2(float a, float b) {
    ull d;
    asm("mov.b64 %0,{%1,%2};" : "=l"(d) : "r"(__float_as_uint(a)), "r"(__float_as_uint(b)));
    return d;
}
__device__ __forceinline__ void unpk2(ull v, float& a, float& b) {
    unsigned int l, h;
    asm("mov.b64 {%0,%1},%2;" : "=r"(l), "=r"(h) : "l"(v));
    a = __uint_as_float(l); b = __uint_as_float(h);
}

// ---------------- scratch ----------------
__device__ float g_h1[NB*NT*NH];
__device__ float g_h2[NB*NT*NH];
__device__ float g_m0[NB*NT];
__device__ float g_center[NB*NT];
__device__ int   g_phs[NB*NW];
__device__ int   g_phc[NB*NW];
__device__ int   g_mels[NB*NW];
__device__ int   g_melc[NB*NW];

// ---------------- conv5 + channel-LN + relu (packed f32x2 over t-pairs) ----------------
// acc2[j] lanes = (t = j, t = j+16), j in 0..15. Tap k reads pair (x[j+k], x[j+16+k]) = sp[j+k].
__global__ void __launch_bounds__(256) conv_ln_relu(
                             const float* __restrict__ in,
                             const float* __restrict__ mask,
                             const float* __restrict__ wgt,   // (O=256, I=256, K=5)
                             const float* __restrict__ bias,
                             const float* __restrict__ lng,
                             const float* __restrict__ lnb,
                             float* __restrict__ out)
{
    const int TT = 32;
    __shared__ ull spu[20 * NH];              // 40 KB; pre-paired (x_j, x_{j+16})
    __shared__ float mu_s[TT], rs_s[TT];

    int b  = blockIdx.x / (NT / TT);
    int t0 = (blockIdx.x % (NT / TT)) * TT;
    int o  = threadIdx.x;

    float* spf = (float*)spu;
    for (int idx = o; idx < 36 * NH; idx += 256) {
        int jp = idx >> 8; int i = idx & 255;   // jp = 0..35 -> x[t0+jp-2]
        int t = t0 + jp - 2;
        float v = 0.0f;
        if (t >= 0 && t < NT) v = in[((size_t)b * NT + t) * NH + i] * mask[b * NT + t];
        if (jp < 20)  spf[(jp * NH + i) * 2]            = v;
        if (jp >= 16) spf[((jp - 16) * NH + i) * 2 + 1] = v;
    }
    __syncthreads();

    ull acc2[16];
    {
        float bo = bias[o];
        ull bp = pk2(bo, bo);
        #pragma unroll
        for (int j = 0; j < 16; j++) acc2[j] = bp;
    }

    const float* wo = wgt + (size_t)o * (NH * 5);
    #pragma unroll 1
    for (int i = 0; i < NH; i++) {
        float w0 = wo[0], w1 = wo[1], w2 = wo[2], w3 = wo[3], w4 = wo[4];
        wo += 5;
        ull W0 = pk2(w0, w0), W1 = pk2(w1, w1), W2 = pk2(w2, w2), W3 = pk2(w3, w3), W4 = pk2(w4, w4);
        ull p0 = spu[i], p1 = spu[NH + i], p2 = spu[2 * NH + i], p3 = spu[3 * NH + i];
        #pragma unroll
        for (int j = 0; j < 16; j++) {
            ull p4 = spu[(j + 4) * NH + i];
            ull s;
            MUL2(s, p0, W0);
            FMA2(s, p1, W1, s);
            FMA2(s, p2, W2, s);
            FMA2(s, p3, W3, s);
            FMA2(s, p4, W4, s);
            ADD2(acc2[j], acc2[j], s);        // acc += s, same order as round 1
            p0 = p1; p1 = p2; p2 = p3; p3 = p4;
        }
    }
    __syncthreads();                          // done reading spu

    float* ys = (float*)spu;                  // alias-reuse: ys[t*NH + c], 32 KB
    #pragma unroll
    for (int j = 0; j < 16; j++) {
        float a, bb;
        unpk2(acc2[j], a, bb);
        ys[j * NH + o]        = a;
        ys[(j + 16) * NH + o] = bb;
    }
    __syncthreads();

    int warp = o >> 5, lane = o & 31;
    for (int t = warp; t < TT; t += 8) {
        float s = 0.0f;
        for (int c = lane; c < NH; c += 32) s += ys[t * NH + c];
        for (int off = 16; off; off >>= 1) s += __shfl_xor_sync(0xffffffffu, s, off);
        float mu = s * (1.0f / NH);
        float v = 0.0f;
        for (int c = lane; c < NH; c += 32) { float d = ys[t * NH + c] - mu; v = fmaf(d, d, v); }
        for (int off = 16; off; off >>= 1) v += __shfl_xor_sync(0xffffffffu, v, off);
        v *= (1.0f / NH);
        if (lane == 0) { mu_s[t] = mu; rs_s[t] = 1.0f / sqrtf(v + 1e-4f); }
    }
    __syncthreads();

    float go = lng[o], b2 = lnb[o];
    #pragma unroll
    for (int t = 0; t < TT; t++) {
        float y = (ys[t * NH + o] - mu_s[t]) * rs_s[t] * go + b2;
        out[((size_t)b * NT + t0 + t) * NH + o] = fmaxf(y, 0.0f);
    }
}

// ---------------- proj 1x1 + residual + gauss ch0 -> m0 (packed + single tree) ----------------
__global__ void __launch_bounds__(256) proj_gauss(
                           const float* __restrict__ x,
                           const float* __restrict__ mask,
                           const float* __restrict__ pw,   // (256,256)
                           const float* __restrict__ pb,
                           const float* __restrict__ gw,   // (2,256)
                           const float* __restrict__ gb)
{
    const int TT = 16;
    __shared__ ull hs2[8 * NH];               // pairs (t, t+8): 16 KB
    __shared__ float red2[256][17];           // padded tree: ~17 KB

    int b  = blockIdx.x / (NT / TT);
    int t0 = (blockIdx.x % (NT / TT)) * TT;
    int o  = threadIdx.x;

    float* hf = (float*)hs2;
    for (int idx = o; idx < TT * NH; idx += 256) {
        int tt = idx >> 8; int i = idx & 255;
        float v = g_h2[((size_t)b * NT + t0 + tt) * NH + i];
        if (tt < 8) hf[(tt * NH + i) * 2]           = v;
        else        hf[((tt - 8) * NH + i) * 2 + 1] = v;
    }
    __syncthreads();

    ull acc2[8];
    {
        float pbo = pb[o];
        ull bp = pk2(pbo, pbo);
        #pragma unroll
        for (int j = 0; j < 8; j++) acc2[j] = bp;
    }

    const float* pwo = pw + (size_t)o * NH;
    #pragma unroll 1
    for (int i = 0; i < NH; i++) {
        float w = pwo[i];
        ull W = pk2(w, w);
        #pragma unroll
        for (int j = 0; j < 8; j++) {
            ull h = hs2[j * NH + i];
            FMA2(acc2[j], W, h, acc2[j]);     // fma(w, h, acc), same as round 1
        }
    }

    float av[16];
    #pragma unroll
    for (int j = 0; j < 8; j++) unpk2(acc2[j], av[j], av[j + 8]);

    float gwo = gw[o];
    #pragma unroll
    for (int t = 0; t < TT; t++) {
        float mt = mask[b * NT + t0 + t];
        float v = (x[((size_t)b * NT + t0 + t) * NH + o] + av[t]) * mt;
        red2[o][t] = gwo * v;
    }
    __syncthreads();

    // identical tree association as round 1 (red[o] += red[o+s]), all 16 t at once
    #pragma unroll
    for (int s = 128; s > 0; s >>= 1) {
        if (o < s) {
            #pragma unroll
            for (int t = 0; t < TT; t++) red2[o][t] += red2[o + s][t];
        }
        __syncthreads();
    }
    if (o < TT) {
        float g0 = red2[0][o] + gb[0];
        float mt = mask[b * NT + t0 + o];
        g_m0[b * NT + t0 + o] = (fmaxf(g0, 0.0f) + 1.0f) * mt;
    }
}

// ---------------- word stats, rescale, cumsum -> center (UNCHANGED math) ----------------
__global__ void stats_kernel(const int* __restrict__ x2w,
                             const int* __restrict__ mel2w,
                             float* __restrict__ mword_out)
{
    int b = blockIdx.x;
    int tid = threadIdx.x;
    __shared__ int   cph[NW], cmel[NW], sph[NW], smel[NW];
    __shared__ float sc[NW];
    __shared__ float mbuf[NT];

    if (tid < NW) { cph[tid] = 0; cmel[tid] = 0; }
    __syncthreads();
    for (int p = tid; p < NT; p += 256) atomicAdd(&cph[x2w[b * NT + p] - 1], 1);
    for (int t = tid; t < NM; t += 256) atomicAdd(&cmel[mel2w[b * NM + t] - 1], 1);
    __syncthreads();
    if (tid == 0) { int s = 0; for (int w = 0; w < NW; w++) { sph[w]  = s; s += cph[w]; } }
    if (tid == 1) { int s = 0; for (int w = 0; w < NW; w++) { smel[w] = s; s += cmel[w]; } }
    __syncthreads();

    if (tid < NW) {
        int w = tid;
        int st = sph[w], c = cph[w];
        float s = 0.0f;
        for (int j = 0; j < c; j++) s += g_m0[b * NT + st + j];
        mword_out[b * NW + w] = s;
        sc[w] = (float)cmel[w] / (s + 1e-4f);
        g_phs[b * NW + w] = st;      g_phc[b * NW + w] = c;
        g_mels[b * NW + w] = smel[w]; g_melc[b * NW + w] = cmel[w];
    }
    __syncthreads();

    for (int p = tid; p < NT; p += 256) {
        int w = x2w[b * NT + p] - 1;
        float m0 = g_m0[b * NT + p];
        float d  = __fmul_rn(sc[w] - 1.0f, m0);
        mbuf[p]  = __fadd_rn(m0, d);
    }
    __syncthreads();

    if (tid == 0) {
        float c = 0.0f;
        for (int p = 0; p < NT; p++) {
            c = __fadd_rn(c, mbuf[p]);
            float half = __fmul_rn(0.5f, mbuf[p]);
            g_center[b * NT + p] = __fadd_rn(c, -half);
        }
    }
}

// ---------------- merged attention: matched rows + missing-word blocks ----------------
__global__ void __launch_bounds__(256) attn_kernel(
                             const float* __restrict__ x,
                             const int* __restrict__ mel2w,
                             float* __restrict__ outA,
                             float* __restrict__ outW)
{
    __shared__ float wsm[8][64];
    __shared__ float wts[8][NT];
    __shared__ float cen[NT];
    __shared__ float redA[8], redB[8];

    const int MBLK = NB * NM / 8;   // 4096
    if (blockIdx.x < MBLK) {
        // ---- matched: one warp per mel row ----
        int warp = threadIdx.x >> 5, lane = threadIdx.x & 31;
        int row = blockIdx.x * 8 + warp;
        int b = row >> 12;
        int t = row & 4095;

        int w = mel2w[(size_t)b * NM + t] - 1;
        int cnt = g_phc[b * NW + w];
        if (cnt == 0) return;
        int lo = g_phs[b * NW + w];
        float tp = (float)t;

        float l0 = -3.4e38f, l1 = -3.4e38f;
        if (lane < cnt) {
            float d = g_center[b * NT + lo + lane] - tp;
            l0 = -(__fmul_rn(d, d)) / 10.0f;
        }
        if (lane + 32 < cnt) {
            float d = g_center[b * NT + lo + lane + 32] - tp;
            l1 = -(__fmul_rn(d, d)) / 10.0f;
        }
        float mx = fmaxf(l0, l1);
        for (int off = 16; off; off >>= 1) mx = fmaxf(mx, __shfl_xor_sync(0xffffffffu, mx, off));
        float e0 = (lane < cnt)      ? expf(l0 - mx) : 0.0f;
        float e1 = (lane + 32 < cnt) ? expf(l1 - mx) : 0.0f;
        float s = e0 + e1;
        for (int off = 16; off; off >>= 1) s += __shfl_xor_sync(0xffffffffu, s, off);
        wsm[warp][lane]      = e0 / s;
        wsm[warp][lane + 32] = e1 / s;
        __syncwarp();

        // vectorized outW: 4 x STG.128 per lane
        size_t wbase = ((size_t)b * NM + t) * NT;
        float4* w4 = (float4*)(outW + wbase);
        #pragma unroll
        for (int q = 0; q < 4; q++) {
            int p = q * 128 + lane * 4;
            float4 v;
            int j0 = p - lo;
            v.x = ((unsigned)(j0)     < (unsigned)cnt) ? wsm[warp][j0]     : 0.0f;
            v.y = ((unsigned)(j0 + 1) < (unsigned)cnt) ? wsm[warp][j0 + 1] : 0.0f;
            v.z = ((unsigned)(j0 + 2) < (unsigned)cnt) ? wsm[warp][j0 + 2] : 0.0f;
            v.w = ((unsigned)(j0 + 3) < (unsigned)cnt) ? wsm[warp][j0 + 3] : 0.0f;
            w4[q * 32 + lane] = v;
        }

        // attn: lane handles channels lane*8 .. lane*8+7 (float4 x2)
        float4 a0 = make_float4(0.f, 0.f, 0.f, 0.f);
        float4 a1 = make_float4(0.f, 0.f, 0.f, 0.f);
        for (int j = 0; j < cnt; j++) {
            float wj = wsm[warp][j];
            const float4* xr = (const float4*)(x + ((size_t)b * NT + lo + j) * NH);
            float4 v0 = xr[lane * 2], v1 = xr[lane * 2 + 1];
            a0.x = fmaf(wj, v0.x, a0.x); a0.y = fmaf(wj, v0.y, a0.y);
            a0.z = fmaf(wj, v0.z, a0.z); a0.w = fmaf(wj, v0.w, a0.w);
            a1.x = fmaf(wj, v1.x, a1.x); a1.y = fmaf(wj, v1.y, a1.y);
            a1.z = fmaf(wj, v1.z, a1.z); a1.w = fmaf(wj, v1.w, a1.w);
        }
        float4* o4 = (float4*)(outA + ((size_t)b * NM + t) * NH);
        o4[lane * 2]     = a0;
        o4[lane * 2 + 1] = a1;
    } else {
        // ---- missing-word blocks ----
        int idx = blockIdx.x - MBLK;
        int w = idx & 255, b = idx >> 8;
        if (g_phc[b * NW + w] != 0) return;
        int mc = g_melc[b * NW + w];
        if (mc == 0) return;
        int ms = g_mels[b * NW + w];

        int tid = threadIdx.x;
        int lane = tid & 31, warp = tid >> 5;

        for (int p = tid; p < NT; p += 256) cen[p] = g_center[b * NT + p];
        __syncthreads();

        for (int r0 = 0; r0 < mc; r0 += 8) {
            int RT = min(8, mc - r0);
            for (int r = 0; r < RT; r++) {
                float tp = (float)(ms + r0 + r);
                float d0 = cen[tid] - tp;
                float lg0 = -(__fmul_rn(d0, d0)) / 10.0f;
                float m0v = __fadd_rn(lg0, -1e9f);
                float d1 = cen[tid + 256] - tp;
                float lg1 = -(__fmul_rn(d1, d1)) / 10.0f;
                float m1v = __fadd_rn(lg1, -1e9f);

                float mx = fmaxf(m0v, m1v);
                for (int off = 16; off; off >>= 1) mx = fmaxf(mx, __shfl_xor_sync(0xffffffffu, mx, off));
                if (lane == 0) redA[warp] = mx;
                __syncthreads();
                float mall = redA[0];
                #pragma unroll
                for (int k = 1; k < 8; k++) mall = fmaxf(mall, redA[k]);

                float e0 = expf(m0v - mall);
                float e1 = expf(m1v - mall);
                float ss = e0 + e1;
                for (int off = 16; off; off >>= 1) ss += __shfl_xor_sync(0xffffffffu, ss, off);
                if (lane == 0) redB[warp] = ss;
                __syncthreads();
                float tot = redB[0];
                #pragma unroll
                for (int k = 1; k < 8; k++) tot += redB[k];

                float w0 = e0 / tot, w1 = e1 / tot;
                wts[r][tid] = w0; wts[r][tid + 256] = w1;
                size_t wb = ((size_t)b * NM + ms + r0 + r) * NT;
                outW[wb + tid] = w0; outW[wb + tid + 256] = w1;
                __syncthreads();
            }
            __syncthreads();

            float a[8];
            #pragma unroll
            for (int r = 0; r < 8; r++) a[r] = 0.0f;
            for (int p = 0; p < NT; p++) {
                float xv = x[((size_t)b * NT + p) * NH + tid];
                #pragma unroll
                for (int r = 0; r < 8; r++) a[r] = fmaf(wts[r][p], xv, a[r]);
            }
            for (int r = 0; r < RT; r++)
                outA[((size_t)b * NM + ms + r0 + r) * NH + tid] = a[r];
            __syncthreads();
        }
    }
}

// ---------------- launcher ----------------
extern "C" void kernel_launch(void* const* d_in, const int* in_sizes, int n_in,
                              void* d_out, int out_size)
{
    const float* x       = (const float*)d_in[0];
    const float* x_mask  = (const float*)d_in[1];
    const float* pre_w1  = (const float*)d_in[2];
    const float* pre_b1  = (const float*)d_in[3];
    const float* ln1_g   = (const float*)d_in[4];
    const float* ln1_b   = (const float*)d_in[5];
    const float* pre_w2  = (const float*)d_in[6];
    const float* pre_b2  = (const float*)d_in[7];
    const float* ln2_g   = (const float*)d_in[8];
    const float* ln2_b   = (const float*)d_in[9];
    const float* proj_w  = (const float*)d_in[10];
    const float* proj_b  = (const float*)d_in[11];
    const float* gauss_w = (const float*)d_in[12];
    const float* gauss_b = (const float*)d_in[13];
    const int*   x2word  = (const int*)d_in[14];
    const int*   mel2word= (const int*)d_in[15];

    float* outA  = (float*)d_out;
    float* outW  = outA + (size_t)NB * NM * NH;
    float* outMW = outW + (size_t)NB * NM * NT;

    float* h1; cudaGetSymbolAddress((void**)&h1, g_h1);
    float* h2; cudaGetSymbolAddress((void**)&h2, g_h2);

    conv_ln_relu<<<NB * (NT / 32), 256>>>(x,  x_mask, pre_w1, pre_b1, ln1_g, ln1_b, h1);
    conv_ln_relu<<<NB * (NT / 32), 256>>>(h1, x_mask, pre_w2, pre_b2, ln2_g, ln2_b, h2);
    proj_gauss  <<<NB * (NT / 16), 256>>>(x, x_mask, proj_w, proj_b, gauss_w, gauss_b);
    stats_kernel<<<NB, 256>>>(x2word, mel2word, outMW);
    attn_kernel <<<NB * NM / 8 + NB * NW, 256>>>(x, mel2word, outA, outW);
}

// round 3
// speedup vs baseline: 2.1426x; 2.1426x over previous
#include <cuda_runtime.h>
#include <math.h>

#define NB 8
#define NT 512
#define NH 256
#define NM 4096
#define NW 256

// ---------------- scratch (device globals: no allocation allowed) ----------------
__device__ float g_h1[NB*NT*NH];
__device__ float g_h2[NB*NT*NH];
__device__ float g_m0[NB*NT];
__device__ float g_center[NB*NT];
__device__ int   g_phs[NB*NW];
__device__ int   g_phc[NB*NW];
__device__ int   g_mels[NB*NW];
__device__ int   g_melc[NB*NW];
__device__ float g_w1T[NH*5*NH];   // [(i*5+k)*NH + o]
__device__ float g_w2T[NH*5*NH];
__device__ float g_pwT[NH*NH];     // [i*NH + o]

// ---------------- weight transpose (coalesced writes) ----------------
__global__ void transpose_weights(const float* __restrict__ w1,
                                  const float* __restrict__ w2,
                                  const float* __restrict__ pw)
{
    int o = threadIdx.x;          // 256
    int j = blockIdx.x;           // 0..2815
    if (j < 1280) {
        g_w1T[j * NH + o] = w1[(size_t)o * 1280 + j];
    } else if (j < 2560) {
        int jj = j - 1280;
        g_w2T[jj * NH + o] = w2[(size_t)o * 1280 + jj];
    } else {
        int jj = j - 2560;
        g_pwT[jj * NH + o] = pw[(size_t)o * NH + jj];
    }
}

// ---------------- conv5 + channel-LN + relu (round-1 math, transposed weights) ----------------
__global__ void __launch_bounds__(256) conv_ln_relu(
                             const float* __restrict__ in,
                             const float* __restrict__ mask,
                             const float* __restrict__ wT,    // [(i*5+k)*NH + o]
                             const float* __restrict__ bias,
                             const float* __restrict__ lng,
                             const float* __restrict__ lnb,
                             float* __restrict__ out)
{
    const int TT = 32;
    __shared__ float xs[TT + 4][NH];
    __shared__ float mu_s[TT], rs_s[TT];

    int b  = blockIdx.x / (NT / TT);
    int t0 = (blockIdx.x % (NT / TT)) * TT;
    int o  = threadIdx.x;

    for (int idx = o; idx < (TT + 4) * NH; idx += 256) {
        int tt = idx >> 8; int i = idx & 255;
        int t = t0 + tt - 2;
        float v = 0.0f;
        if (t >= 0 && t < NT) v = in[((size_t)b * NT + t) * NH + i] * mask[b * NT + t];
        xs[tt][i] = v;
    }
    __syncthreads();

    float acc[TT];
    float bo = bias[o];
    #pragma unroll
    for (int t = 0; t < TT; t++) acc[t] = bo;

    const float* wp = wT + o;
    #pragma unroll 2
    for (int i = 0; i < NH; i++) {
        float w0 = wp[0], w1 = wp[NH], w2 = wp[2*NH], w3 = wp[3*NH], w4 = wp[4*NH];
        wp += 5 * NH;
        float x0 = xs[0][i], x1 = xs[1][i], x2 = xs[2][i], x3 = xs[3][i];
        #pragma unroll
        for (int t = 0; t < TT; t++) {
            float x4 = xs[t + 4][i];
            float s = x0 * w0;
            s = fmaf(x1, w1, s);
            s = fmaf(x2, w2, s);
            s = fmaf(x3, w3, s);
            s = fmaf(x4, w4, s);
            acc[t] += s;
            x0 = x1; x1 = x2; x2 = x3; x3 = x4;
        }
    }
    __syncthreads();

    float (*ys)[NH] = (float(*)[NH])xs;
    #pragma unroll
    for (int t = 0; t < TT; t++) ys[t][o] = acc[t];
    __syncthreads();

    int warp = o >> 5, lane = o & 31;
    for (int t = warp; t < TT; t += 8) {
        float s = 0.0f;
        for (int c = lane; c < NH; c += 32) s += ys[t][c];
        for (int off = 16; off; off >>= 1) s += __shfl_xor_sync(0xffffffffu, s, off);
        float mu = s * (1.0f / NH);
        float v = 0.0f;
        for (int c = lane; c < NH; c += 32) { float d = ys[t][c] - mu; v = fmaf(d, d, v); }
        for (int off = 16; off; off >>= 1) v += __shfl_xor_sync(0xffffffffu, v, off);
        v *= (1.0f / NH);
        if (lane == 0) { mu_s[t] = mu; rs_s[t] = 1.0f / sqrtf(v + 1e-4f); }
    }
    __syncthreads();

    float go = lng[o], b2 = lnb[o];
    #pragma unroll
    for (int t = 0; t < TT; t++) {
        float y = (ys[t][o] - mu_s[t]) * rs_s[t] * go + b2;
        out[((size_t)b * NT + t0 + t) * NH + o] = fmaxf(y, 0.0f);
    }
}

// ---------------- proj 1x1 + residual + gauss ch0 -> m0 ----------------
__global__ void __launch_bounds__(256) proj_gauss(
                           const float* __restrict__ x,
                           const float* __restrict__ mask,
                           const float* __restrict__ pb,
                           const float* __restrict__ gw,
                           const float* __restrict__ gb)
{
    const int TT = 16;
    __shared__ float hs[TT][NH];
    __shared__ float red2[256][TT + 1];

    int b  = blockIdx.x / (NT / TT);
    int t0 = (blockIdx.x % (NT / TT)) * TT;
    int o  = threadIdx.x;

    for (int idx = o; idx < TT * NH; idx += 256) {
        int tt = idx >> 8; int i = idx & 255;
        hs[tt][i] = g_h2[((size_t)b * NT + t0 + tt) * NH + i];
    }
    __syncthreads();

    float acc[TT];
    float pbo = pb[o];
    #pragma unroll
    for (int t = 0; t < TT; t++) acc[t] = pbo;

    const float* pwp = g_pwT + o;
    for (int i = 0; i < NH; i++) {
        float w = pwp[i * NH];
        #pragma unroll
        for (int t = 0; t < TT; t++) acc[t] = fmaf(w, hs[t][i], acc[t]);
    }

    float gwo = gw[o];
    #pragma unroll
    for (int t = 0; t < TT; t++) {
        float mt = mask[b * NT + t0 + t];
        float v = (x[((size_t)b * NT + t0 + t) * NH + o] + acc[t]) * mt;
        red2[o][t] = gwo * v;
    }
    __syncthreads();

    // same per-(o,t) association as round 1's per-t tree (verified bit-identical in R2)
    #pragma unroll
    for (int s = 128; s > 0; s >>= 1) {
        if (o < s) {
            #pragma unroll
            for (int t = 0; t < TT; t++) red2[o][t] += red2[o + s][t];
        }
        __syncthreads();
    }
    if (o < TT) {
        float g0 = red2[0][o] + gb[0];
        float mt = mask[b * NT + t0 + o];
        g_m0[b * NT + t0 + o] = (fmaxf(g0, 0.0f) + 1.0f) * mt;
    }
}

// ---------------- word stats, rescale, cumsum -> center (UNCHANGED) ----------------
__global__ void stats_kernel(const int* __restrict__ x2w,
                             const int* __restrict__ mel2w,
                             float* __restrict__ mword_out)
{
    int b = blockIdx.x;
    int tid = threadIdx.x;
    __shared__ int   cph[NW], cmel[NW], sph[NW], smel[NW];
    __shared__ float sc[NW];
    __shared__ float mbuf[NT];

    if (tid < NW) { cph[tid] = 0; cmel[tid] = 0; }
    __syncthreads();
    for (int p = tid; p < NT; p += 256) atomicAdd(&cph[x2w[b * NT + p] - 1], 1);
    for (int t = tid; t < NM; t += 256) atomicAdd(&cmel[mel2w[b * NM + t] - 1], 1);
    __syncthreads();
    if (tid == 0) { int s = 0; for (int w = 0; w < NW; w++) { sph[w]  = s; s += cph[w]; } }
    if (tid == 1) { int s = 0; for (int w = 0; w < NW; w++) { smel[w] = s; s += cmel[w]; } }
    __syncthreads();

    if (tid < NW) {
        int w = tid;
        int st = sph[w], c = cph[w];
        float s = 0.0f;
        for (int j = 0; j < c; j++) s += g_m0[b * NT + st + j];
        mword_out[b * NW + w] = s;
        sc[w] = (float)cmel[w] / (s + 1e-4f);
        g_phs[b * NW + w] = st;      g_phc[b * NW + w] = c;
        g_mels[b * NW + w] = smel[w]; g_melc[b * NW + w] = cmel[w];
    }
    __syncthreads();

    for (int p = tid; p < NT; p += 256) {
        int w = x2w[b * NT + p] - 1;
        float m0 = g_m0[b * NT + p];
        float d  = __fmul_rn(sc[w] - 1.0f, m0);
        mbuf[p]  = __fadd_rn(m0, d);
    }
    __syncthreads();

    if (tid == 0) {
        float c = 0.0f;
        for (int p = 0; p < NT; p++) {
            c = __fadd_rn(c, mbuf[p]);
            float half = __fmul_rn(0.5f, mbuf[p]);
            g_center[b * NT + p] = __fadd_rn(c, -half);
        }
    }
}

// ---------------- matched rows: 1 warp per mel row (round-1 exact) ----------------
__global__ void attn_matched(const float* __restrict__ x,
                             const int* __restrict__ mel2w,
                             float* __restrict__ outA,
                             float* __restrict__ outW)
{
    __shared__ float wsm[8][64];
    int warp = threadIdx.x >> 5, lane = threadIdx.x & 31;
    int row = blockIdx.x * 8 + warp;
    int b = row >> 12;
    int t = row & 4095;

    int w = mel2w[(size_t)b * NM + t] - 1;
    int cnt = g_phc[b * NW + w];
    if (cnt == 0) return;
    int lo = g_phs[b * NW + w];
    float tp = (float)t;

    float l0 = -3.4e38f, l1 = -3.4e38f;
    if (lane < cnt) {
        float d = g_center[b * NT + lo + lane] - tp;
        l0 = -(__fmul_rn(d, d)) / 10.0f;
    }
    if (lane + 32 < cnt) {
        float d = g_center[b * NT + lo + lane + 32] - tp;
        l1 = -(__fmul_rn(d, d)) / 10.0f;
    }
    float mx = fmaxf(l0, l1);
    for (int off = 16; off; off >>= 1) mx = fmaxf(mx, __shfl_xor_sync(0xffffffffu, mx, off));
    float e0 = (lane < cnt)      ? expf(l0 - mx) : 0.0f;
    float e1 = (lane + 32 < cnt) ? expf(l1 - mx) : 0.0f;
    float s = e0 + e1;
    for (int off = 16; off; off >>= 1) s += __shfl_xor_sync(0xffffffffu, s, off);
    wsm[warp][lane]      = e0 / s;
    wsm[warp][lane + 32] = e1 / s;
    __syncwarp();

    size_t wbase = ((size_t)b * NM + t) * NT;
    #pragma unroll
    for (int q = 0; q < 16; q++) {
        int p = lane + q * 32;
        int j = p - lo;
        float v = (j >= 0 && j < cnt) ? wsm[warp][j] : 0.0f;
        outW[wbase + p] = v;
    }

    float a[8];
    #pragma unroll
    for (int q = 0; q < 8; q++) a[q] = 0.0f;
    for (int j = 0; j < cnt; j++) {
        float wj = wsm[warp][j];
        const float* xr = x + ((size_t)b * NT + lo + j) * NH;
        #pragma unroll
        for (int q = 0; q < 8; q++) a[q] = fmaf(wj, xr[lane + q * 32], a[q]);
    }
    size_t abase = ((size_t)b * NM + t) * NH;
    #pragma unroll
    for (int q = 0; q < 8; q++) outA[abase + lane + q * 32] = a[q];
}

// ---------------- missing-word rows (round-1 exact) ----------------
__global__ void attn_missing(const float* __restrict__ x,
                             float* __restrict__ outA,
                             float* __restrict__ outW)
{
    int w = blockIdx.x, b = blockIdx.y;
    if (g_phc[b * NW + w] != 0) return;
    int mc = g_melc[b * NW + w];
    if (mc == 0) return;
    int ms = g_mels[b * NW + w];

    int tid = threadIdx.x;
    int lane = tid & 31, warp = tid >> 5;
    __shared__ float wts[8][NT];
    __shared__ float cen[NT];
    __shared__ float redA[8], redB[8];

    for (int p = tid; p < NT; p += 256) cen[p] = g_center[b * NT + p];
    __syncthreads();

    for (int r0 = 0; r0 < mc; r0 += 8) {
        int RT = min(8, mc - r0);
        for (int r = 0; r < RT; r++) {
            float tp = (float)(ms + r0 + r);
            float d0 = cen[tid] - tp;
            float lg0 = -(__fmul_rn(d0, d0)) / 10.0f;
            float m0v = __fadd_rn(lg0, -1e9f);
            float d1 = cen[tid + 256] - tp;
            float lg1 = -(__fmul_rn(d1, d1)) / 10.0f;
            float m1v = __fadd_rn(lg1, -1e9f);

            float mx = fmaxf(m0v, m1v);
            for (int off = 16; off; off >>= 1) mx = fmaxf(mx, __shfl_xor_sync(0xffffffffu, mx, off));
            if (lane == 0) redA[warp] = mx;
            __syncthreads();
            float mall = redA[0];
            #pragma unroll
            for (int k = 1; k < 8; k++) mall = fmaxf(mall, redA[k]);

            float e0 = expf(m0v - mall);
            float e1 = expf(m1v - mall);
            float ss = e0 + e1;
            for (int off = 16; off; off >>= 1) ss += __shfl_xor_sync(0xffffffffu, ss, off);
            if (lane == 0) redB[warp] = ss;
            __syncthreads();
            float tot = redB[0];
            #pragma unroll
            for (int k = 1; k < 8; k++) tot += redB[k];

            float w0 = e0 / tot, w1 = e1 / tot;
            wts[r][tid] = w0; wts[r][tid + 256] = w1;
            size_t wb = ((size_t)b * NM + ms + r0 + r) * NT;
            outW[wb + tid] = w0; outW[wb + tid + 256] = w1;
            __syncthreads();
        }
        __syncthreads();

        float a[8];
        #pragma unroll
        for (int r = 0; r < 8; r++) a[r] = 0.0f;
        for (int p = 0; p < NT; p++) {
            float xv = x[((size_t)b * NT + p) * NH + tid];
            #pragma unroll
            for (int r = 0; r < 8; r++) a[r] = fmaf(wts[r][p], xv, a[r]);
        }
        for (int r = 0; r < RT; r++)
            outA[((size_t)b * NM + ms + r0 + r) * NH + tid] = a[r];
        __syncthreads();
    }
}

// ---------------- launcher ----------------
extern "C" void kernel_launch(void* const* d_in, const int* in_sizes, int n_in,
                              void* d_out, int out_size)
{
    const float* x       = (const float*)d_in[0];
    const float* x_mask  = (const float*)d_in[1];
    const float* pre_w1  = (const float*)d_in[2];
    const float* pre_b1  = (const float*)d_in[3];
    const float* ln1_g   = (const float*)d_in[4];
    const float* ln1_b   = (const float*)d_in[5];
    const float* pre_w2  = (const float*)d_in[6];
    const float* pre_b2  = (const float*)d_in[7];
    const float* ln2_g   = (const float*)d_in[8];
    const float* ln2_b   = (const float*)d_in[9];
    const float* proj_w  = (const float*)d_in[10];
    const float* proj_b  = (const float*)d_in[11];
    const float* gauss_w = (const float*)d_in[12];
    const float* gauss_b = (const float*)d_in[13];
    const int*   x2word  = (const int*)d_in[14];
    const int*   mel2word= (const int*)d_in[15];

    float* outA  = (float*)d_out;
    float* outW  = outA + (size_t)NB * NM * NH;
    float* outMW = outW + (size_t)NB * NM * NT;

    float* h1;  cudaGetSymbolAddress((void**)&h1,  g_h1);
    float* h2;  cudaGetSymbolAddress((void**)&h2,  g_h2);
    float* w1T; cudaGetSymbolAddress((void**)&w1T, g_w1T);
    float* w2T; cudaGetSymbolAddress((void**)&w2T, g_w2T);

    transpose_weights<<<2816, 256>>>(pre_w1, pre_w2, proj_w);
    conv_ln_relu<<<NB * (NT / 32), 256>>>(x,  x_mask, w1T, pre_b1, ln1_g, ln1_b, h1);
    conv_ln_relu<<<NB * (NT / 32), 256>>>(h1, x_mask, w2T, pre_b2, ln2_g, ln2_b, h2);
    proj_gauss  <<<NB * (NT / 16), 256>>>(x, x_mask, proj_b, gauss_w, gauss_b);
    stats_kernel<<<NB, 256>>>(x2word, mel2word, outMW);
    attn_matched<<<NB * NM / 8, 256>>>(x, mel2word, outA, outW);
    attn_missing<<<dim3(NW, NB), 256>>>(x, outA, outW);
}

// round 4
// speedup vs baseline: 2.3390x; 1.0917x over previous
#include <cuda_runtime.h>
#include <math.h>

#define NB 8
#define NT 512
#define NH 256
#define NM 4096
#define NW 256

typedef unsigned long long ull;

#define FMA2(d,a,b,c) asm("fma.rn.f32x2 %0,%1,%2,%3;" : "=l"(d) : "l"(a), "l"(b), "l"(c))
#define MUL2(d,a,b)   asm("mul.rn.f32x2 %0,%1,%2;"    : "=l"(d) : "l"(a), "l"(b))
#define ADD2(d,a,b)   asm("add.rn.f32x2 %0,%1,%2;"    : "=l"(d) : "l"(a), "l"(b))

__device__ __forceinline__ ull pk2(float a, float b) {
    ull d;
    asm("mov.b64 %0,{%1,%2};" : "=l"(d) : "r"(__float_as_uint(a)), "r"(__float_as_uint(b)));
    return d;
}
__device__ __forceinline__ void unpk2(ull v, float& a, float& b) {
    unsigned int l, h;
    asm("mov.b64 {%0,%1},%2;" : "=r"(l), "=r"(h) : "l"(v));
    a = __uint_as_float(l); b = __uint_as_float(h);
}

// ---------------- scratch ----------------
__device__ float g_h1[NB*NT*NH];
__device__ float g_h2[NB*NT*NH];
__device__ float g_m0[NB*NT];
__device__ float g_center[NB*NT];
__device__ int   g_phs[NB*NW];
__device__ int   g_phc[NB*NW];
__device__ int   g_mels[NB*NW];
__device__ int   g_melc[NB*NW];
__device__ float g_w1T[NH*5*NH];   // [(i*5+k)*NH + o]
__device__ float g_w2T[NH*5*NH];
__device__ float g_pwT[NH*NH];     // [i*NH + o]

// ---------------- weight transpose ----------------
__global__ void transpose_weights(const float* __restrict__ w1,
                                  const float* __restrict__ w2,
                                  const float* __restrict__ pw)
{
    int o = threadIdx.x;
    int j = blockIdx.x;
    if (j < 1280) {
        g_w1T[j * NH + o] = w1[(size_t)o * 1280 + j];
    } else if (j < 2560) {
        int jj = j - 1280;
        g_w2T[jj * NH + o] = w2[(size_t)o * 1280 + jj];
    } else {
        int jj = j - 2560;
        g_pwT[jj * NH + o] = pw[(size_t)o * NH + jj];
    }
}

// ---------------- conv5 + channel-LN + relu: f32x2 over t-pairs, transposed weights ----------------
// acc2[j] lanes = (t=j, t=j+16). Per-lane op order identical to round-1 scalar version.
__global__ void __launch_bounds__(256) conv_ln_relu(
                             const float* __restrict__ in,
                             const float* __restrict__ mask,
                             const float* __restrict__ wT,    // [(i*5+k)*NH + o]
                             const float* __restrict__ bias,
                             const float* __restrict__ lng,
                             const float* __restrict__ lnb,
                             float* __restrict__ out)
{
    const int TT = 32;
    __shared__ ull spu[20 * NH];              // 40 KB, pre-paired (x_j, x_{j+16})
    __shared__ float mu_s[TT], rs_s[TT];

    int b  = blockIdx.x / (NT / TT);
    int t0 = (blockIdx.x % (NT / TT)) * TT;
    int o  = threadIdx.x;

    float* spf = (float*)spu;
    for (int idx = o; idx < 36 * NH; idx += 256) {
        int jp = idx >> 8; int i = idx & 255;   // jp -> x[t0+jp-2]
        int t = t0 + jp - 2;
        float v = 0.0f;
        if (t >= 0 && t < NT) v = in[((size_t)b * NT + t) * NH + i] * mask[b * NT + t];
        if (jp < 20)  spf[(jp * NH + i) * 2]            = v;
        if (jp >= 16) spf[((jp - 16) * NH + i) * 2 + 1] = v;
    }
    __syncthreads();

    ull acc2[16];
    {
        float bo = bias[o];
        ull bp = pk2(bo, bo);
        #pragma unroll
        for (int j = 0; j < 16; j++) acc2[j] = bp;
    }

    const float* wp = wT + o;
    #pragma unroll 2
    for (int i = 0; i < NH; i++) {
        float w0 = wp[0], w1 = wp[NH], w2 = wp[2*NH], w3 = wp[3*NH], w4 = wp[4*NH];
        wp += 5 * NH;
        ull W0 = pk2(w0, w0), W1 = pk2(w1, w1), W2 = pk2(w2, w2), W3 = pk2(w3, w3), W4 = pk2(w4, w4);
        ull p0 = spu[i], p1 = spu[NH + i], p2 = spu[2 * NH + i], p3 = spu[3 * NH + i];
        #pragma unroll
        for (int j = 0; j < 16; j++) {
            ull p4 = spu[(j + 4) * NH + i];
            ull s;
            MUL2(s, p0, W0);
            FMA2(s, p1, W1, s);
            FMA2(s, p2, W2, s);
            FMA2(s, p3, W3, s);
            FMA2(s, p4, W4, s);
            ADD2(acc2[j], acc2[j], s);
            p0 = p1; p1 = p2; p2 = p3; p3 = p4;
        }
    }
    __syncthreads();

    float* ys = (float*)spu;                  // reuse as ys[t*NH + c]
    #pragma unroll
    for (int j = 0; j < 16; j++) {
        float a, bb;
        unpk2(acc2[j], a, bb);
        ys[j * NH + o]        = a;
        ys[(j + 16) * NH + o] = bb;
    }
    __syncthreads();

    int warp = o >> 5, lane = o & 31;
    for (int t = warp; t < TT; t += 8) {
        float s = 0.0f;
        for (int c = lane; c < NH; c += 32) s += ys[t * NH + c];
        for (int off = 16; off; off >>= 1) s += __shfl_xor_sync(0xffffffffu, s, off);
        float mu = s * (1.0f / NH);
        float v = 0.0f;
        for (int c = lane; c < NH; c += 32) { float d = ys[t * NH + c] - mu; v = fmaf(d, d, v); }
        for (int off = 16; off; off >>= 1) v += __shfl_xor_sync(0xffffffffu, v, off);
        v *= (1.0f / NH);
        if (lane == 0) { mu_s[t] = mu; rs_s[t] = 1.0f / sqrtf(v + 1e-4f); }
    }
    __syncthreads();

    float go = lng[o], b2 = lnb[o];
    #pragma unroll
    for (int t = 0; t < TT; t++) {
        float y = (ys[t * NH + o] - mu_s[t]) * rs_s[t] * go + b2;
        out[((size_t)b * NT + t0 + t) * NH + o] = fmaxf(y, 0.0f);
    }
}

// ---------------- proj 1x1 + residual + gauss ch0 -> m0 (hs transposed for LDS.128) ----------------
__global__ void __launch_bounds__(256) proj_gauss(
                           const float* __restrict__ x,
                           const float* __restrict__ mask,
                           const float* __restrict__ pb,
                           const float* __restrict__ gw,
                           const float* __restrict__ gb)
{
    const int TT = 16;
    __shared__ float hsT[NH][TT];             // [i][t], 16 KB
    __shared__ float red2[256][TT + 1];

    int b  = blockIdx.x / (NT / TT);
    int t0 = (blockIdx.x % (NT / TT)) * TT;
    int o  = threadIdx.x;

    for (int idx = o; idx < TT * NH; idx += 256) {
        int tt = idx >> 8; int i = idx & 255;
        hsT[i][tt] = g_h2[((size_t)b * NT + t0 + tt) * NH + i];
    }
    __syncthreads();

    float acc[TT];
    float pbo = pb[o];
    #pragma unroll
    for (int t = 0; t < TT; t++) acc[t] = pbo;

    const float* pwp = g_pwT + o;
    #pragma unroll 2
    for (int i = 0; i < NH; i++) {
        float w = pwp[i * NH];
        const float4* h4 = (const float4*)hsT[i];
        #pragma unroll
        for (int q = 0; q < 4; q++) {
            float4 h = h4[q];
            acc[q*4+0] = fmaf(w, h.x, acc[q*4+0]);
            acc[q*4+1] = fmaf(w, h.y, acc[q*4+1]);
            acc[q*4+2] = fmaf(w, h.z, acc[q*4+2]);
            acc[q*4+3] = fmaf(w, h.w, acc[q*4+3]);
        }
    }

    float gwo = gw[o];
    #pragma unroll
    for (int t = 0; t < TT; t++) {
        float mt = mask[b * NT + t0 + t];
        float v = (x[((size_t)b * NT + t0 + t) * NH + o] + acc[t]) * mt;
        red2[o][t] = gwo * v;
    }
    __syncthreads();

    #pragma unroll
    for (int s = 128; s > 0; s >>= 1) {
        if (o < s) {
            #pragma unroll
            for (int t = 0; t < TT; t++) red2[o][t] += red2[o + s][t];
        }
        __syncthreads();
    }
    if (o < TT) {
        float g0 = red2[0][o] + gb[0];
        float mt = mask[b * NT + t0 + o];
        g_m0[b * NT + t0 + o] = (fmaxf(g0, 0.0f) + 1.0f) * mt;
    }
}

// ---------------- word stats, rescale, cumsum -> center (UNCHANGED) ----------------
__global__ void stats_kernel(const int* __restrict__ x2w,
                             const int* __restrict__ mel2w,
                             float* __restrict__ mword_out)
{
    int b = blockIdx.x;
    int tid = threadIdx.x;
    __shared__ int   cph[NW], cmel[NW], sph[NW], smel[NW];
    __shared__ float sc[NW];
    __shared__ float mbuf[NT];

    if (tid < NW) { cph[tid] = 0; cmel[tid] = 0; }
    __syncthreads();
    for (int p = tid; p < NT; p += 256) atomicAdd(&cph[x2w[b * NT + p] - 1], 1);
    for (int t = tid; t < NM; t += 256) atomicAdd(&cmel[mel2w[b * NM + t] - 1], 1);
    __syncthreads();
    if (tid == 0) { int s = 0; for (int w = 0; w < NW; w++) { sph[w]  = s; s += cph[w]; } }
    if (tid == 1) { int s = 0; for (int w = 0; w < NW; w++) { smel[w] = s; s += cmel[w]; } }
    __syncthreads();

    if (tid < NW) {
        int w = tid;
        int st = sph[w], c = cph[w];
        float s = 0.0f;
        for (int j = 0; j < c; j++) s += g_m0[b * NT + st + j];
        mword_out[b * NW + w] = s;
        sc[w] = (float)cmel[w] / (s + 1e-4f);
        g_phs[b * NW + w] = st;      g_phc[b * NW + w] = c;
        g_mels[b * NW + w] = smel[w]; g_melc[b * NW + w] = cmel[w];
    }
    __syncthreads();

    for (int p = tid; p < NT; p += 256) {
        int w = x2w[b * NT + p] - 1;
        float m0 = g_m0[b * NT + p];
        float d  = __fmul_rn(sc[w] - 1.0f, m0);
        mbuf[p]  = __fadd_rn(m0, d);
    }
    __syncthreads();

    if (tid == 0) {
        float c = 0.0f;
        for (int p = 0; p < NT; p++) {
            c = __fadd_rn(c, mbuf[p]);
            float half = __fmul_rn(0.5f, mbuf[p]);
            g_center[b * NT + p] = __fadd_rn(c, -half);
        }
    }
}

// ---------------- matched rows: 1 warp per mel row (UNCHANGED) ----------------
__global__ void attn_matched(const float* __restrict__ x,
                             const int* __restrict__ mel2w,
                             float* __restrict__ outA,
                             float* __restrict__ outW)
{
    __shared__ float wsm[8][64];
    int warp = threadIdx.x >> 5, lane = threadIdx.x & 31;
    int row = blockIdx.x * 8 + warp;
    int b = row >> 12;
    int t = row & 4095;

    int w = mel2w[(size_t)b * NM + t] - 1;
    int cnt = g_phc[b * NW + w];
    if (cnt == 0) return;
    int lo = g_phs[b * NW + w];
    float tp = (float)t;

    float l0 = -3.4e38f, l1 = -3.4e38f;
    if (lane < cnt) {
        float d = g_center[b * NT + lo + lane] - tp;
        l0 = -(__fmul_rn(d, d)) / 10.0f;
    }
    if (lane + 32 < cnt) {
        float d = g_center[b * NT + lo + lane + 32] - tp;
        l1 = -(__fmul_rn(d, d)) / 10.0f;
    }
    float mx = fmaxf(l0, l1);
    for (int off = 16; off; off >>= 1) mx = fmaxf(mx, __shfl_xor_sync(0xffffffffu, mx, off));
    float e0 = (lane < cnt)      ? expf(l0 - mx) : 0.0f;
    float e1 = (lane + 32 < cnt) ? expf(l1 - mx) : 0.0f;
    float s = e0 + e1;
    for (int off = 16; off; off >>= 1) s += __shfl_xor_sync(0xffffffffu, s, off);
    wsm[warp][lane]      = e0 / s;
    wsm[warp][lane + 32] = e1 / s;
    __syncwarp();

    size_t wbase = ((size_t)b * NM + t) * NT;
    #pragma unroll
    for (int q = 0; q < 16; q++) {
        int p = lane + q * 32;
        int j = p - lo;
        float v = (j >= 0 && j < cnt) ? wsm[warp][j] : 0.0f;
        outW[wbase + p] = v;
    }

    float a[8];
    #pragma unroll
    for (int q = 0; q < 8; q++) a[q] = 0.0f;
    for (int j = 0; j < cnt; j++) {
        float wj = wsm[warp][j];
        const float* xr = x + ((size_t)b * NT + lo + j) * NH;
        #pragma unroll
        for (int q = 0; q < 8; q++) a[q] = fmaf(wj, xr[lane + q * 32], a[q]);
    }
    size_t abase = ((size_t)b * NM + t) * NH;
    #pragma unroll
    for (int q = 0; q < 8; q++) outA[abase + lane + q * 32] = a[q];
}

// ---------------- missing-word rows (UNCHANGED) ----------------
__global__ void attn_missing(const float* __restrict__ x,
                             float* __restrict__ outA,
                             float* __restrict__ outW)
{
    int w = blockIdx.x, b = blockIdx.y;
    if (g_phc[b * NW + w] != 0) return;
    int mc = g_melc[b * NW + w];
    if (mc == 0) return;
    int ms = g_mels[b * NW + w];

    int tid = threadIdx.x;
    int lane = tid & 31, warp = tid >> 5;
    __shared__ float wts[8][NT];
    __shared__ float cen[NT];
    __shared__ float redA[8], redB[8];

    for (int p = tid; p < NT; p += 256) cen[p] = g_center[b * NT + p];
    __syncthreads();

    for (int r0 = 0; r0 < mc; r0 += 8) {
        int RT = min(8, mc - r0);
        for (int r = 0; r < RT; r++) {
            float tp = (float)(ms + r0 + r);
            float d0 = cen[tid] - tp;
            float lg0 = -(__fmul_rn(d0, d0)) / 10.0f;
            float m0v = __fadd_rn(lg0, -1e9f);
            float d1 = cen[tid + 256] - tp;
            float lg1 = -(__fmul_rn(d1, d1)) / 10.0f;
            float m1v = __fadd_rn(lg1, -1e9f);

            float mx = fmaxf(m0v, m1v);
            for (int off = 16; off; off >>= 1) mx = fmaxf(mx, __shfl_xor_sync(0xffffffffu, mx, off));
            if (lane == 0) redA[warp] = mx;
            __syncthreads();
            float mall = redA[0];
            #pragma unroll
            for (int k = 1; k < 8; k++) mall = fmaxf(mall, redA[k]);

            float e0 = expf(m0v - mall);
            float e1 = expf(m1v - mall);
            float ss = e0 + e1;
            for (int off = 16; off; off >>= 1) ss += __shfl_xor_sync(0xffffffffu, ss, off);
            if (lane == 0) redB[warp] = ss;
            __syncthreads();
            float tot = redB[0];
            #pragma unroll
            for (int k = 1; k < 8; k++) tot += redB[k];

            float w0 = e0 / tot, w1 = e1 / tot;
            wts[r][tid] = w0; wts[r][tid + 256] = w1;
            size_t wb = ((size_t)b * NM + ms + r0 + r) * NT;
            outW[wb + tid] = w0; outW[wb + tid + 256] = w1;
            __syncthreads();
        }
        __syncthreads();

        float a[8];
        #pragma unroll
        for (int r = 0; r < 8; r++) a[r] = 0.0f;
        for (int p = 0; p < NT; p++) {
            float xv = x[((size_t)b * NT + p) * NH + tid];
            #pragma unroll
            for (int r = 0; r < 8; r++) a[r] = fmaf(wts[r][p], xv, a[r]);
        }
        for (int r = 0; r < RT; r++)
            outA[((size_t)b * NM + ms + r0 + r) * NH + tid] = a[r];
        __syncthreads();
    }
}

// ---------------- launcher ----------------
extern "C" void kernel_launch(void* const* d_in, const int* in_sizes, int n_in,
                              void* d_out, int out_size)
{
    const float* x       = (const float*)d_in[0];
    const float* x_mask  = (const float*)d_in[1];
    const float* pre_w1  = (const float*)d_in[2];
    const float* pre_b1  = (const float*)d_in[3];
    const float* ln1_g   = (const float*)d_in[4];
    const float* ln1_b   = (const float*)d_in[5];
    const float* pre_w2  = (const float*)d_in[6];
    const float* pre_b2  = (const float*)d_in[7];
    const float* ln2_g   = (const float*)d_in[8];
    const float* ln2_b   = (const float*)d_in[9];
    const float* proj_w  = (const float*)d_in[10];
    const float* proj_b  = (const float*)d_in[11];
    const float* gauss_w = (const float*)d_in[12];
    const float* gauss_b = (const float*)d_in[13];
    const int*   x2word  = (const int*)d_in[14];
    const int*   mel2word= (const int*)d_in[15];

    float* outA  = (float*)d_out;
    float* outW  = outA + (size_t)NB * NM * NH;
    float* outMW = outW + (size_t)NB * NM * NT;

    float* h1;  cudaGetSymbolAddress((void**)&h1,  g_h1);
    float* h2;  cudaGetSymbolAddress((void**)&h2,  g_h2);
    float* w1T; cudaGetSymbolAddress((void**)&w1T, g_w1T);
    float* w2T; cudaGetSymbolAddress((void**)&w2T, g_w2T);

    transpose_weights<<<2816, 256>>>(pre_w1, pre_w2, proj_w);
    conv_ln_relu<<<NB * (NT / 32), 256>>>(x,  x_mask, w1T, pre_b1, ln1_g, ln1_b, h1);
    conv_ln_relu<<<NB * (NT / 32), 256>>>(h1, x_mask, w2T, pre_b2, ln2_g, ln2_b, h2);
    proj_gauss  <<<NB * (NT / 16), 256>>>(x, x_mask, proj_b, gauss_w, gauss_b);
    stats_kernel<<<NB, 256>>>(x2word, mel2word, outMW);
    attn_matched<<<NB * NM / 8, 256>>>(x, mel2word, outA, outW);
    attn_missing<<<dim3(NW, NB), 256>>>(x, outA, outW);
}

// round 5
// speedup vs baseline: 2.9797x; 1.2740x over previous
#include <cuda_runtime.h>
#include <math.h>

#define NB 8
#define NT 512
#define NH 256
#define NM 4096
#define NW 256

typedef unsigned long long ull;

#define FMA2(d,a,b,c) asm("fma.rn.f32x2 %0,%1,%2,%3;" : "=l"(d) : "l"(a), "l"(b), "l"(c))
#define MUL2(d,a,b)   asm("mul.rn.f32x2 %0,%1,%2;"    : "=l"(d) : "l"(a), "l"(b))
#define ADD2(d,a,b)   asm("add.rn.f32x2 %0,%1,%2;"    : "=l"(d) : "l"(a), "l"(b))

__device__ __forceinline__ ull pk2(float a, float b) {
    ull d;
    asm("mov.b64 %0,{%1,%2};" : "=l"(d) : "r"(__float_as_uint(a)), "r"(__float_as_uint(b)));
    return d;
}
__device__ __forceinline__ void unpk2(ull v, float& a, float& b) {
    unsigned int l, h;
    asm("mov.b64 {%0,%1},%2;" : "=r"(l), "=r"(h) : "l"(v));
    a = __uint_as_float(l); b = __uint_as_float(h);
}

// ---------------- scratch ----------------
__device__ float g_h1[NB*NT*NH];
__device__ float g_h2[NB*NT*NH];
__device__ float g_m0[NB*NT];
__device__ float g_center[NB*NT];
__device__ int   g_phs[NB*NW];
__device__ int   g_phc[NB*NW];
__device__ int   g_mels[NB*NW];
__device__ int   g_melc[NB*NW];
__device__ float g_w1T[NH*5*NH];   // [(i*5+k)*NH + o]
__device__ float g_w2T[NH*5*NH];
__device__ float g_pwT[NH*NH];     // [i*NH + o]

// ---------------- weight transpose ----------------
__global__ void transpose_weights(const float* __restrict__ w1,
                                  const float* __restrict__ w2,
                                  const float* __restrict__ pw)
{
    int o = threadIdx.x;
    int j = blockIdx.x;
    if (j < 1280) {
        g_w1T[j * NH + o] = w1[(size_t)o * 1280 + j];
    } else if (j < 2560) {
        int jj = j - 1280;
        g_w2T[jj * NH + o] = w2[(size_t)o * 1280 + jj];
    } else {
        int jj = j - 2560;
        g_pwT[jj * NH + o] = pw[(size_t)o * NH + jj];
    }
}

// ---------------- conv5 + channel-LN + relu: f32x2 over t-pairs, transposed weights ----------------
__global__ void __launch_bounds__(256) conv_ln_relu(
                             const float* __restrict__ in,
                             const float* __restrict__ mask,
                             const float* __restrict__ wT,
                             const float* __restrict__ bias,
                             const float* __restrict__ lng,
                             const float* __restrict__ lnb,
                             float* __restrict__ out)
{
    const int TT = 32;
    __shared__ ull spu[20 * NH];
    __shared__ float mu_s[TT], rs_s[TT];

    int b  = blockIdx.x / (NT / TT);
    int t0 = (blockIdx.x % (NT / TT)) * TT;
    int o  = threadIdx.x;

    float* spf = (float*)spu;
    for (int idx = o; idx < 36 * NH; idx += 256) {
        int jp = idx >> 8; int i = idx & 255;
        int t = t0 + jp - 2;
        float v = 0.0f;
        if (t >= 0 && t < NT) v = in[((size_t)b * NT + t) * NH + i] * mask[b * NT + t];
        if (jp < 20)  spf[(jp * NH + i) * 2]            = v;
        if (jp >= 16) spf[((jp - 16) * NH + i) * 2 + 1] = v;
    }
    __syncthreads();

    ull acc2[16];
    {
        float bo = bias[o];
        ull bp = pk2(bo, bo);
        #pragma unroll
        for (int j = 0; j < 16; j++) acc2[j] = bp;
    }

    const float* wp = wT + o;
    #pragma unroll 2
    for (int i = 0; i < NH; i++) {
        float w0 = wp[0], w1 = wp[NH], w2 = wp[2*NH], w3 = wp[3*NH], w4 = wp[4*NH];
        wp += 5 * NH;
        ull W0 = pk2(w0, w0), W1 = pk2(w1, w1), W2 = pk2(w2, w2), W3 = pk2(w3, w3), W4 = pk2(w4, w4);
        ull p0 = spu[i], p1 = spu[NH + i], p2 = spu[2 * NH + i], p3 = spu[3 * NH + i];
        #pragma unroll
        for (int j = 0; j < 16; j++) {
            ull p4 = spu[(j + 4) * NH + i];
            ull s;
            MUL2(s, p0, W0);
            FMA2(s, p1, W1, s);
            FMA2(s, p2, W2, s);
            FMA2(s, p3, W3, s);
            FMA2(s, p4, W4, s);
            ADD2(acc2[j], acc2[j], s);
            p0 = p1; p1 = p2; p2 = p3; p3 = p4;
        }
    }
    __syncthreads();

    float* ys = (float*)spu;
    #pragma unroll
    for (int j = 0; j < 16; j++) {
        float a, bb;
        unpk2(acc2[j], a, bb);
        ys[j * NH + o]        = a;
        ys[(j + 16) * NH + o] = bb;
    }
    __syncthreads();

    int warp = o >> 5, lane = o & 31;
    for (int t = warp; t < TT; t += 8) {
        float s = 0.0f;
        for (int c = lane; c < NH; c += 32) s += ys[t * NH + c];
        for (int off = 16; off; off >>= 1) s += __shfl_xor_sync(0xffffffffu, s, off);
        float mu = s * (1.0f / NH);
        float v = 0.0f;
        for (int c = lane; c < NH; c += 32) { float d = ys[t * NH + c] - mu; v = fmaf(d, d, v); }
        for (int off = 16; off; off >>= 1) v += __shfl_xor_sync(0xffffffffu, v, off);
        v *= (1.0f / NH);
        if (lane == 0) { mu_s[t] = mu; rs_s[t] = 1.0f / sqrtf(v + 1e-4f); }
    }
    __syncthreads();

    float go = lng[o], b2 = lnb[o];
    #pragma unroll
    for (int t = 0; t < TT; t++) {
        float y = (ys[t * NH + o] - mu_s[t]) * rs_s[t] * go + b2;
        out[((size_t)b * NT + t0 + t) * NH + o] = fmaxf(y, 0.0f);
    }
}

// ---------------- proj 1x1 + residual + gauss ch0 -> m0: f32x2 (R2-proven) + coalesced pwT ----------------
__global__ void __launch_bounds__(256) proj_gauss(
                           const float* __restrict__ x,
                           const float* __restrict__ mask,
                           const float* __restrict__ pb,
                           const float* __restrict__ gw,
                           const float* __restrict__ gb)
{
    const int TT = 16;
    __shared__ ull hs2[8 * NH];               // pairs (t, t+8), 16 KB
    __shared__ float red2[256][TT + 1];

    int b  = blockIdx.x / (NT / TT);
    int t0 = (blockIdx.x % (NT / TT)) * TT;
    int o  = threadIdx.x;

    float* hf = (float*)hs2;
    for (int idx = o; idx < TT * NH; idx += 256) {
        int tt = idx >> 8; int i = idx & 255;
        float v = g_h2[((size_t)b * NT + t0 + tt) * NH + i];
        if (tt < 8) hf[(tt * NH + i) * 2]           = v;
        else        hf[((tt - 8) * NH + i) * 2 + 1] = v;
    }
    __syncthreads();

    ull acc2[8];
    {
        float pbo = pb[o];
        ull bp = pk2(pbo, pbo);
        #pragma unroll
        for (int j = 0; j < 8; j++) acc2[j] = bp;
    }

    const float* pwp = g_pwT + o;
    #pragma unroll 2
    for (int i = 0; i < NH; i++) {
        float w = pwp[i * NH];                // coalesced across o
        ull W = pk2(w, w);
        #pragma unroll
        for (int j = 0; j < 8; j++) {
            ull h = hs2[j * NH + i];
            FMA2(acc2[j], W, h, acc2[j]);     // fma(w,h,acc), per-lane order as R1
        }
    }

    float av[16];
    #pragma unroll
    for (int j = 0; j < 8; j++) unpk2(acc2[j], av[j], av[j + 8]);

    float gwo = gw[o];
    #pragma unroll
    for (int t = 0; t < TT; t++) {
        float mt = mask[b * NT + t0 + t];
        float v = (x[((size_t)b * NT + t0 + t) * NH + o] + av[t]) * mt;
        red2[o][t] = gwo * v;
    }
    __syncthreads();

    #pragma unroll
    for (int s = 128; s > 0; s >>= 1) {
        if (o < s) {
            #pragma unroll
            for (int t = 0; t < TT; t++) red2[o][t] += red2[o + s][t];
        }
        __syncthreads();
    }
    if (o < TT) {
        float g0 = red2[0][o] + gb[0];
        float mt = mask[b * NT + t0 + o];
        g_m0[b * NT + t0 + o] = (fmaxf(g0, 0.0f) + 1.0f) * mt;
    }
}

// ---------------- word stats, rescale, cumsum -> center (UNCHANGED) ----------------
__global__ void stats_kernel(const int* __restrict__ x2w,
                             const int* __restrict__ mel2w,
                             float* __restrict__ mword_out)
{
    int b = blockIdx.x;
    int tid = threadIdx.x;
    __shared__ int   cph[NW], cmel[NW], sph[NW], smel[NW];
    __shared__ float sc[NW];
    __shared__ float mbuf[NT];

    if (tid < NW) { cph[tid] = 0; cmel[tid] = 0; }
    __syncthreads();
    for (int p = tid; p < NT; p += 256) atomicAdd(&cph[x2w[b * NT + p] - 1], 1);
    for (int t = tid; t < NM; t += 256) atomicAdd(&cmel[mel2w[b * NM + t] - 1], 1);
    __syncthreads();
    if (tid == 0) { int s = 0; for (int w = 0; w < NW; w++) { sph[w]  = s; s += cph[w]; } }
    if (tid == 1) { int s = 0; for (int w = 0; w < NW; w++) { smel[w] = s; s += cmel[w]; } }
    __syncthreads();

    if (tid < NW) {
        int w = tid;
        int st = sph[w], c = cph[w];
        float s = 0.0f;
        for (int j = 0; j < c; j++) s += g_m0[b * NT + st + j];
        mword_out[b * NW + w] = s;
        sc[w] = (float)cmel[w] / (s + 1e-4f);
        g_phs[b * NW + w] = st;      g_phc[b * NW + w] = c;
        g_mels[b * NW + w] = smel[w]; g_melc[b * NW + w] = cmel[w];
    }
    __syncthreads();

    for (int p = tid; p < NT; p += 256) {
        int w = x2w[b * NT + p] - 1;
        float m0 = g_m0[b * NT + p];
        float d  = __fmul_rn(sc[w] - 1.0f, m0);
        mbuf[p]  = __fadd_rn(m0, d);
    }
    __syncthreads();

    if (tid == 0) {
        float c = 0.0f;
        for (int p = 0; p < NT; p++) {
            c = __fadd_rn(c, mbuf[p]);
            float half = __fmul_rn(0.5f, mbuf[p]);
            g_center[b * NT + p] = __fadd_rn(c, -half);
        }
    }
}

// ---------------- matched rows: 1 warp per mel row (float4 outW stores) ----------------
__global__ void attn_matched(const float* __restrict__ x,
                             const int* __restrict__ mel2w,
                             float* __restrict__ outA,
                             float* __restrict__ outW)
{
    __shared__ float wsm[8][64];
    int warp = threadIdx.x >> 5, lane = threadIdx.x & 31;
    int row = blockIdx.x * 8 + warp;
    int b = row >> 12;
    int t = row & 4095;

    int w = mel2w[(size_t)b * NM + t] - 1;
    int cnt = g_phc[b * NW + w];
    if (cnt == 0) return;
    int lo = g_phs[b * NW + w];
    float tp = (float)t;

    float l0 = -3.4e38f, l1 = -3.4e38f;
    if (lane < cnt) {
        float d = g_center[b * NT + lo + lane] - tp;
        l0 = -(__fmul_rn(d, d)) / 10.0f;
    }
    if (lane + 32 < cnt) {
        float d = g_center[b * NT + lo + lane + 32] - tp;
        l1 = -(__fmul_rn(d, d)) / 10.0f;
    }
    float mx = fmaxf(l0, l1);
    for (int off = 16; off; off >>= 1) mx = fmaxf(mx, __shfl_xor_sync(0xffffffffu, mx, off));
    float e0 = (lane < cnt)      ? expf(l0 - mx) : 0.0f;
    float e1 = (lane + 32 < cnt) ? expf(l1 - mx) : 0.0f;
    float s = e0 + e1;
    for (int off = 16; off; off >>= 1) s += __shfl_xor_sync(0xffffffffu, s, off);
    wsm[warp][lane]      = e0 / s;
    wsm[warp][lane + 32] = e1 / s;
    __syncwarp();

    // identical values, vectorized stores
    size_t wbase = ((size_t)b * NM + t) * NT;
    float4* w4 = (float4*)(outW + wbase);
    #pragma unroll
    for (int q = 0; q < 4; q++) {
        int p = q * 128 + lane * 4;
        int j0 = p - lo;
        float4 v;
        v.x = ((unsigned)(j0)     < (unsigned)cnt) ? wsm[warp][j0]     : 0.0f;
        v.y = ((unsigned)(j0 + 1) < (unsigned)cnt) ? wsm[warp][j0 + 1] : 0.0f;
        v.z = ((unsigned)(j0 + 2) < (unsigned)cnt) ? wsm[warp][j0 + 2] : 0.0f;
        v.w = ((unsigned)(j0 + 3) < (unsigned)cnt) ? wsm[warp][j0 + 3] : 0.0f;
        w4[q * 32 + lane] = v;
    }

    float a[8];
    #pragma unroll
    for (int q = 0; q < 8; q++) a[q] = 0.0f;
    for (int j = 0; j < cnt; j++) {
        float wj = wsm[warp][j];
        const float* xr = x + ((size_t)b * NT + lo + j) * NH;
        #pragma unroll
        for (int q = 0; q < 8; q++) a[q] = fmaf(wj, xr[lane + q * 32], a[q]);
    }
    size_t abase = ((size_t)b * NM + t) * NH;
    #pragma unroll
    for (int q = 0; q < 8; q++) outA[abase + lane + q * 32] = a[q];
}

// ---------------- missing-word rows: chunk-split across gridDim.z ----------------
__global__ void attn_missing(const float* __restrict__ x,
                             float* __restrict__ outA,
                             float* __restrict__ outW)
{
    int w = blockIdx.x, b = blockIdx.y, z = blockIdx.z;
    if (g_phc[b * NW + w] != 0) return;
    int mc = g_melc[b * NW + w];
    if (mc == 0) return;
    int ms = g_mels[b * NW + w];

    int tid = threadIdx.x;
    int lane = tid & 31, warp = tid >> 5;
    __shared__ float wts[8][NT];
    __shared__ float cen[NT];
    __shared__ float redA[8], redB[8];

    for (int p = tid; p < NT; p += 256) cen[p] = g_center[b * NT + p];
    __syncthreads();

    // grid-stride over 8-row chunks: z, z+4, z+8, ... (gridDim.z = 4)
    for (int r0 = z * 8; r0 < mc; r0 += 32) {
        int RT = min(8, mc - r0);
        for (int r = 0; r < RT; r++) {
            float tp = (float)(ms + r0 + r);
            float d0 = cen[tid] - tp;
            float lg0 = -(__fmul_rn(d0, d0)) / 10.0f;
            float m0v = __fadd_rn(lg0, -1e9f);
            float d1 = cen[tid + 256] - tp;
            float lg1 = -(__fmul_rn(d1, d1)) / 10.0f;
            float m1v = __fadd_rn(lg1, -1e9f);

            float mx = fmaxf(m0v, m1v);
            for (int off = 16; off; off >>= 1) mx = fmaxf(mx, __shfl_xor_sync(0xffffffffu, mx, off));
            if (lane == 0) redA[warp] = mx;
            __syncthreads();
            float mall = redA[0];
            #pragma unroll
            for (int k = 1; k < 8; k++) mall = fmaxf(mall, redA[k]);

            float e0 = expf(m0v - mall);
            float e1 = expf(m1v - mall);
            float ss = e0 + e1;
            for (int off = 16; off; off >>= 1) ss += __shfl_xor_sync(0xffffffffu, ss, off);
            if (lane == 0) redB[warp] = ss;
            __syncthreads();
            float tot = redB[0];
            #pragma unroll
            for (int k = 1; k < 8; k++) tot += redB[k];

            float w0 = e0 / tot, w1 = e1 / tot;
            wts[r][tid] = w0; wts[r][tid + 256] = w1;
            size_t wb = ((size_t)b * NM + ms + r0 + r) * NT;
            outW[wb + tid] = w0; outW[wb + tid + 256] = w1;
            __syncthreads();
        }
        __syncthreads();

        float a[8];
        #pragma unroll
        for (int r = 0; r < 8; r++) a[r] = 0.0f;
        for (int p = 0; p < NT; p++) {
            float xv = x[((size_t)b * NT + p) * NH + tid];
            #pragma unroll
            for (int r = 0; r < 8; r++) a[r] = fmaf(wts[r][p], xv, a[r]);
        }
        for (int r = 0; r < RT; r++)
            outA[((size_t)b * NM + ms + r0 + r) * NH + tid] = a[r];
        __syncthreads();
    }
}

// ---------------- launcher ----------------
extern "C" void kernel_launch(void* const* d_in, const int* in_sizes, int n_in,
                              void* d_out, int out_size)
{
    const float* x       = (const float*)d_in[0];
    const float* x_mask  = (const float*)d_in[1];
    const float* pre_w1  = (const float*)d_in[2];
    const float* pre_b1  = (const float*)d_in[3];
    const float* ln1_g   = (const float*)d_in[4];
    const float* ln1_b   = (const float*)d_in[5];
    const float* pre_w2  = (const float*)d_in[6];
    const float* pre_b2  = (const float*)d_in[7];
    const float* ln2_g   = (const float*)d_in[8];
    const float* ln2_b   = (const float*)d_in[9];
    const float* proj_w  = (const float*)d_in[10];
    const float* proj_b  = (const float*)d_in[11];
    const float* gauss_w = (const float*)d_in[12];
    const float* gauss_b = (const float*)d_in[13];
    const int*   x2word  = (const int*)d_in[14];
    const int*   mel2word= (const int*)d_in[15];

    float* outA  = (float*)d_out;
    float* outW  = outA + (size_t)NB * NM * NH;
    float* outMW = outW + (size_t)NB * NM * NT;

    float* h1;  cudaGetSymbolAddress((void**)&h1,  g_h1);
    float* h2;  cudaGetSymbolAddress((void**)&h2,  g_h2);
    float* w1T; cudaGetSymbolAddress((void**)&w1T, g_w1T);
    float* w2T; cudaGetSymbolAddress((void**)&w2T, g_w2T);

    transpose_weights<<<2816, 256>>>(pre_w1, pre_w2, proj_w);
    conv_ln_relu<<<NB * (NT / 32), 256>>>(x,  x_mask, w1T, pre_b1, ln1_g, ln1_b, h1);
    conv_ln_relu<<<NB * (NT / 32), 256>>>(h1, x_mask, w2T, pre_b2, ln2_g, ln2_b, h2);
    proj_gauss  <<<NB * (NT / 16), 256>>>(x, x_mask, proj_b, gauss_w, gauss_b);
    stats_kernel<<<NB, 256>>>(x2word, mel2word, outMW);
    attn_matched<<<NB * NM / 8, 256>>>(x, mel2word, outA, outW);
    attn_missing<<<dim3(NW, NB, 4), 256>>>(x, outA, outW);
}

// round 6
// speedup vs baseline: 3.1165x; 1.0459x over previous
#include <cuda_runtime.h>
#include <math.h>

#define NB 8
#define NT 512
#define NH 256
#define NM 4096
#define NW 256

typedef unsigned long long ull;

#define FMA2(d,a,b,c) asm("fma.rn.f32x2 %0,%1,%2,%3;" : "=l"(d) : "l"(a), "l"(b), "l"(c))
#define MUL2(d,a,b)   asm("mul.rn.f32x2 %0,%1,%2;"    : "=l"(d) : "l"(a), "l"(b))
#define ADD2(d,a,b)   asm("add.rn.f32x2 %0,%1,%2;"    : "=l"(d) : "l"(a), "l"(b))

__device__ __forceinline__ ull pk2(float a, float b) {
    ull d;
    asm("mov.b64 %0,{%1,%2};" : "=l"(d) : "r"(__float_as_uint(a)), "r"(__float_as_uint(b)));
    return d;
}
__device__ __forceinline__ void unpk2(ull v, float& a, float& b) {
    unsigned int l, h;
    asm("mov.b64 {%0,%1},%2;" : "=r"(l), "=r"(h) : "l"(v));
    a = __uint_as_float(l); b = __uint_as_float(h);
}

// ---------------- scratch ----------------
__device__ float g_h1[NB*NT*NH];
__device__ float g_h2[NB*NT*NH];
__device__ float g_m0[NB*NT];
__device__ float g_center[NB*NT];
__device__ int   g_phs[NB*NW];
__device__ int   g_phc[NB*NW];
__device__ int   g_mels[NB*NW];
__device__ int   g_melc[NB*NW];
__device__ int   g_cmel[NB*NW];    // mel histogram (pre-counted)
__device__ float g_w1T[NH*5*NH];   // [(i*5+k)*NH + o]
__device__ float g_w2T[NH*5*NH];
__device__ float g_pwT[NH*NH];     // [i*NH + o]

// ---------------- weight transpose + cmel zero ----------------
__global__ void transpose_weights(const float* __restrict__ w1,
                                  const float* __restrict__ w2,
                                  const float* __restrict__ pw)
{
    int o = threadIdx.x;
    int j = blockIdx.x;
    if (j < 1280) {
        g_w1T[j * NH + o] = w1[(size_t)o * 1280 + j];
    } else if (j < 2560) {
        int jj = j - 1280;
        g_w2T[jj * NH + o] = w2[(size_t)o * 1280 + jj];
    } else if (j < 2816) {
        int jj = j - 2560;
        g_pwT[jj * NH + o] = pw[(size_t)o * NH + jj];
    } else {
        int b = j - 2816;           // 8 blocks zero the mel histogram
        g_cmel[b * NW + o] = 0;
    }
}

// ---------------- parallel mel histogram ----------------
__global__ void mel_hist(const int* __restrict__ mel2w)
{
    int b = blockIdx.y;
    int t = blockIdx.x * 256 + threadIdx.x;   // gridDim.x = NM/256 = 16
    int w = mel2w[(size_t)b * NM + t] - 1;
    atomicAdd(&g_cmel[b * NW + w], 1);
}

// ---------------- conv5 + channel-LN + relu: f32x2 over t-pairs, transposed weights ----------------
__global__ void __launch_bounds__(256) conv_ln_relu(
                             const float* __restrict__ in,
                             const float* __restrict__ mask,
                             const float* __restrict__ wT,
                             const float* __restrict__ bias,
                             const float* __restrict__ lng,
                             const float* __restrict__ lnb,
                             float* __restrict__ out)
{
    const int TT = 32;
    __shared__ ull spu[20 * NH];
    __shared__ float mu_s[TT], rs_s[TT];

    int b  = blockIdx.x / (NT / TT);
    int t0 = (blockIdx.x % (NT / TT)) * TT;
    int o  = threadIdx.x;

    float* spf = (float*)spu;
    for (int idx = o; idx < 36 * NH; idx += 256) {
        int jp = idx >> 8; int i = idx & 255;
        int t = t0 + jp - 2;
        float v = 0.0f;
        if (t >= 0 && t < NT) v = in[((size_t)b * NT + t) * NH + i] * mask[b * NT + t];
        if (jp < 20)  spf[(jp * NH + i) * 2]            = v;
        if (jp >= 16) spf[((jp - 16) * NH + i) * 2 + 1] = v;
    }
    __syncthreads();

    ull acc2[16];
    {
        float bo = bias[o];
        ull bp = pk2(bo, bo);
        #pragma unroll
        for (int j = 0; j < 16; j++) acc2[j] = bp;
    }

    const float* wp = wT + o;
    #pragma unroll 2
    for (int i = 0; i < NH; i++) {
        float w0 = wp[0], w1 = wp[NH], w2 = wp[2*NH], w3 = wp[3*NH], w4 = wp[4*NH];
        wp += 5 * NH;
        ull W0 = pk2(w0, w0), W1 = pk2(w1, w1), W2 = pk2(w2, w2), W3 = pk2(w3, w3), W4 = pk2(w4, w4);
        ull p0 = spu[i], p1 = spu[NH + i], p2 = spu[2 * NH + i], p3 = spu[3 * NH + i];
        #pragma unroll
        for (int j = 0; j < 16; j++) {
            ull p4 = spu[(j + 4) * NH + i];
            ull s;
            MUL2(s, p0, W0);
            FMA2(s, p1, W1, s);
            FMA2(s, p2, W2, s);
            FMA2(s, p3, W3, s);
            FMA2(s, p4, W4, s);
            ADD2(acc2[j], acc2[j], s);
            p0 = p1; p1 = p2; p2 = p3; p3 = p4;
        }
    }
    __syncthreads();

    float* ys = (float*)spu;
    #pragma unroll
    for (int j = 0; j < 16; j++) {
        float a, bb;
        unpk2(acc2[j], a, bb);
        ys[j * NH + o]        = a;
        ys[(j + 16) * NH + o] = bb;
    }
    __syncthreads();

    int warp = o >> 5, lane = o & 31;
    for (int t = warp; t < TT; t += 8) {
        float s = 0.0f;
        for (int c = lane; c < NH; c += 32) s += ys[t * NH + c];
        for (int off = 16; off; off >>= 1) s += __shfl_xor_sync(0xffffffffu, s, off);
        float mu = s * (1.0f / NH);
        float v = 0.0f;
        for (int c = lane; c < NH; c += 32) { float d = ys[t * NH + c] - mu; v = fmaf(d, d, v); }
        for (int off = 16; off; off >>= 1) v += __shfl_xor_sync(0xffffffffu, v, off);
        v *= (1.0f / NH);
        if (lane == 0) { mu_s[t] = mu; rs_s[t] = 1.0f / sqrtf(v + 1e-4f); }
    }
    __syncthreads();

    float go = lng[o], b2 = lnb[o];
    #pragma unroll
    for (int t = 0; t < TT; t++) {
        float y = (ys[t * NH + o] - mu_s[t]) * rs_s[t] * go + b2;
        out[((size_t)b * NT + t0 + t) * NH + o] = fmaxf(y, 0.0f);
    }
}

// ---------------- proj 1x1 + residual + gauss ch0 -> m0 (R3 exact, 45.5us measured) ----------------
__global__ void __launch_bounds__(256) proj_gauss(
                           const float* __restrict__ x,
                           const float* __restrict__ mask,
                           const float* __restrict__ pb,
                           const float* __restrict__ gw,
                           const float* __restrict__ gb)
{
    const int TT = 16;
    __shared__ float hs[TT][NH];
    __shared__ float red2[256][TT + 1];

    int b  = blockIdx.x / (NT / TT);
    int t0 = (blockIdx.x % (NT / TT)) * TT;
    int o  = threadIdx.x;

    for (int idx = o; idx < TT * NH; idx += 256) {
        int tt = idx >> 8; int i = idx & 255;
        hs[tt][i] = g_h2[((size_t)b * NT + t0 + tt) * NH + i];
    }
    __syncthreads();

    float acc[TT];
    float pbo = pb[o];
    #pragma unroll
    for (int t = 0; t < TT; t++) acc[t] = pbo;

    const float* pwp = g_pwT + o;
    for (int i = 0; i < NH; i++) {
        float w = pwp[i * NH];
        #pragma unroll
        for (int t = 0; t < TT; t++) acc[t] = fmaf(w, hs[t][i], acc[t]);
    }

    float gwo = gw[o];
    #pragma unroll
    for (int t = 0; t < TT; t++) {
        float mt = mask[b * NT + t0 + t];
        float v = (x[((size_t)b * NT + t0 + t) * NH + o] + acc[t]) * mt;
        red2[o][t] = gwo * v;
    }
    __syncthreads();

    #pragma unroll
    for (int s = 128; s > 0; s >>= 1) {
        if (o < s) {
            #pragma unroll
            for (int t = 0; t < TT; t++) red2[o][t] += red2[o + s][t];
        }
        __syncthreads();
    }
    if (o < TT) {
        float g0 = red2[0][o] + gb[0];
        float mt = mask[b * NT + t0 + o];
        g_m0[b * NT + t0 + o] = (fmaxf(g0, 0.0f) + 1.0f) * mt;
    }
}

// ---------------- word stats, rescale, cumsum -> center ----------------
__global__ void stats_kernel(const int* __restrict__ x2w,
                             float* __restrict__ mword_out)
{
    int b = blockIdx.x;
    int tid = threadIdx.x;
    __shared__ int   cph[NW], sph[NW], smel[NW];
    __shared__ float sc[NW];
    __shared__ float mbuf[NT];

    if (tid < NW) cph[tid] = 0;
    __syncthreads();
    for (int p = tid; p < NT; p += 256) atomicAdd(&cph[x2w[b * NT + p] - 1], 1);
    __syncthreads();
    if (tid == 0) { int s = 0; for (int w = 0; w < NW; w++) { sph[w]  = s; s += cph[w]; } }
    if (tid == 1) { int s = 0; for (int w = 0; w < NW; w++) { smel[w] = s; s += g_cmel[b * NW + w]; } }
    __syncthreads();

    if (tid < NW) {
        int w = tid;
        int st = sph[w], c = cph[w];
        int cm = g_cmel[b * NW + w];
        float s = 0.0f;
        for (int j = 0; j < c; j++) s += g_m0[b * NT + st + j];
        mword_out[b * NW + w] = s;
        sc[w] = (float)cm / (s + 1e-4f);
        g_phs[b * NW + w] = st;      g_phc[b * NW + w] = c;
        g_mels[b * NW + w] = smel[w]; g_melc[b * NW + w] = cm;
    }
    __syncthreads();

    for (int p = tid; p < NT; p += 256) {
        int w = x2w[b * NT + p] - 1;
        float m0 = g_m0[b * NT + p];
        float d  = __fmul_rn(sc[w] - 1.0f, m0);
        mbuf[p]  = __fadd_rn(m0, d);
    }
    __syncthreads();

    if (tid == 0) {
        float c = 0.0f;
        for (int p = 0; p < NT; p++) {
            c = __fadd_rn(c, mbuf[p]);
            float half = __fmul_rn(0.5f, mbuf[p]);
            g_center[b * NT + p] = __fadd_rn(c, -half);
        }
    }
}

// ---------------- matched rows: 1 warp per mel row (float4 I/O) ----------------
__global__ void attn_matched(const float* __restrict__ x,
                             const int* __restrict__ mel2w,
                             float* __restrict__ outA,
                             float* __restrict__ outW)
{
    __shared__ float wsm[8][64];
    int warp = threadIdx.x >> 5, lane = threadIdx.x & 31;
    int row = blockIdx.x * 8 + warp;
    int b = row >> 12;
    int t = row & 4095;

    int w = mel2w[(size_t)b * NM + t] - 1;
    int cnt = g_phc[b * NW + w];
    if (cnt == 0) return;
    int lo = g_phs[b * NW + w];
    float tp = (float)t;

    float l0 = -3.4e38f, l1 = -3.4e38f;
    if (lane < cnt) {
        float d = g_center[b * NT + lo + lane] - tp;
        l0 = -(__fmul_rn(d, d)) / 10.0f;
    }
    if (lane + 32 < cnt) {
        float d = g_center[b * NT + lo + lane + 32] - tp;
        l1 = -(__fmul_rn(d, d)) / 10.0f;
    }
    float mx = fmaxf(l0, l1);
    for (int off = 16; off; off >>= 1) mx = fmaxf(mx, __shfl_xor_sync(0xffffffffu, mx, off));
    float e0 = (lane < cnt)      ? expf(l0 - mx) : 0.0f;
    float e1 = (lane + 32 < cnt) ? expf(l1 - mx) : 0.0f;
    float s = e0 + e1;
    for (int off = 16; off; off >>= 1) s += __shfl_xor_sync(0xffffffffu, s, off);
    wsm[warp][lane]      = e0 / s;
    wsm[warp][lane + 32] = e1 / s;
    __syncwarp();

    size_t wbase = ((size_t)b * NM + t) * NT;
    float4* w4 = (float4*)(outW + wbase);
    #pragma unroll
    for (int q = 0; q < 4; q++) {
        int p = q * 128 + lane * 4;
        int j0 = p - lo;
        float4 v;
        v.x = ((unsigned)(j0)     < (unsigned)cnt) ? wsm[warp][j0]     : 0.0f;
        v.y = ((unsigned)(j0 + 1) < (unsigned)cnt) ? wsm[warp][j0 + 1] : 0.0f;
        v.z = ((unsigned)(j0 + 2) < (unsigned)cnt) ? wsm[warp][j0 + 2] : 0.0f;
        v.w = ((unsigned)(j0 + 3) < (unsigned)cnt) ? wsm[warp][j0 + 3] : 0.0f;
        w4[q * 32 + lane] = v;
    }

    // per-channel fma sequence unchanged; channels remapped to float4 lanes (R2-proven identical)
    float4 a0 = make_float4(0.f, 0.f, 0.f, 0.f);
    float4 a1 = make_float4(0.f, 0.f, 0.f, 0.f);
    for (int j = 0; j < cnt; j++) {
        float wj = wsm[warp][j];
        const float4* xr = (const float4*)(x + ((size_t)b * NT + lo + j) * NH);
        float4 v0 = xr[lane * 2], v1 = xr[lane * 2 + 1];
        a0.x = fmaf(wj, v0.x, a0.x); a0.y = fmaf(wj, v0.y, a0.y);
        a0.z = fmaf(wj, v0.z, a0.z); a0.w = fmaf(wj, v0.w, a0.w);
        a1.x = fmaf(wj, v1.x, a1.x); a1.y = fmaf(wj, v1.y, a1.y);
        a1.z = fmaf(wj, v1.z, a1.z); a1.w = fmaf(wj, v1.w, a1.w);
    }
    float4* o4 = (float4*)(outA + ((size_t)b * NM + t) * NH);
    o4[lane * 2]     = a0;
    o4[lane * 2 + 1] = a1;
}

// ---------------- missing-word rows: chunk-split across gridDim.z ----------------
__global__ void attn_missing(const float* __restrict__ x,
                             float* __restrict__ outA,
                             float* __restrict__ outW)
{
    int w = blockIdx.x, b = blockIdx.y, z = blockIdx.z;
    if (g_phc[b * NW + w] != 0) return;
    int mc = g_melc[b * NW + w];
    if (mc == 0) return;
    int ms = g_mels[b * NW + w];

    int tid = threadIdx.x;
    int lane = tid & 31, warp = tid >> 5;
    __shared__ float wts[8][NT];
    __shared__ float cen[NT];
    __shared__ float redA[8], redB[8];

    for (int p = tid; p < NT; p += 256) cen[p] = g_center[b * NT + p];
    __syncthreads();

    for (int r0 = z * 8; r0 < mc; r0 += 32) {
        int RT = min(8, mc - r0);
        for (int r = 0; r < RT; r++) {
            float tp = (float)(ms + r0 + r);
            float d0 = cen[tid] - tp;
            float lg0 = -(__fmul_rn(d0, d0)) / 10.0f;
            float m0v = __fadd_rn(lg0, -1e9f);
            float d1 = cen[tid + 256] - tp;
            float lg1 = -(__fmul_rn(d1, d1)) / 10.0f;
            float m1v = __fadd_rn(lg1, -1e9f);

            float mx = fmaxf(m0v, m1v);
            for (int off = 16; off; off >>= 1) mx = fmaxf(mx, __shfl_xor_sync(0xffffffffu, mx, off));
            if (lane == 0) redA[warp] = mx;
            __syncthreads();
            float mall = redA[0];
            #pragma unroll
            for (int k = 1; k < 8; k++) mall = fmaxf(mall, redA[k]);

            float e0 = expf(m0v - mall);
            float e1 = expf(m1v - mall);
            float ss = e0 + e1;
            for (int off = 16; off; off >>= 1) ss += __shfl_xor_sync(0xffffffffu, ss, off);
            if (lane == 0) redB[warp] = ss;
            __syncthreads();
            float tot = redB[0];
            #pragma unroll
            for (int k = 1; k < 8; k++) tot += redB[k];

            float w0 = e0 / tot, w1 = e1 / tot;
            wts[r][tid] = w0; wts[r][tid + 256] = w1;
            size_t wb = ((size_t)b * NM + ms + r0 + r) * NT;
            outW[wb + tid] = w0; outW[wb + tid + 256] = w1;
            __syncthreads();
        }
        __syncthreads();

        float a[8];
        #pragma unroll
        for (int r = 0; r < 8; r++) a[r] = 0.0f;
        for (int p = 0; p < NT; p++) {
            float xv = x[((size_t)b * NT + p) * NH + tid];
            #pragma unroll
            for (int r = 0; r < 8; r++) a[r] = fmaf(wts[r][p], xv, a[r]);
        }
        for (int r = 0; r < RT; r++)
            outA[((size_t)b * NM + ms + r0 + r) * NH + tid] = a[r];
        __syncthreads();
    }
}

// ---------------- launcher ----------------
extern "C" void kernel_launch(void* const* d_in, const int* in_sizes, int n_in,
                              void* d_out, int out_size)
{
    const float* x       = (const float*)d_in[0];
    const float* x_mask  = (const float*)d_in[1];
    const float* pre_w1  = (const float*)d_in[2];
    const float* pre_b1  = (const float*)d_in[3];
    const float* ln1_g   = (const float*)d_in[4];
    const float* ln1_b   = (const float*)d_in[5];
    const float* pre_w2  = (const float*)d_in[6];
    const float* pre_b2  = (const float*)d_in[7];
    const float* ln2_g   = (const float*)d_in[8];
    const float* ln2_b   = (const float*)d_in[9];
    const float* proj_w  = (const float*)d_in[10];
    const float* proj_b  = (const float*)d_in[11];
    const float* gauss_w = (const float*)d_in[12];
    const float* gauss_b = (const float*)d_in[13];
    const int*   x2word  = (const int*)d_in[14];
    const int*   mel2word= (const int*)d_in[15];

    float* outA  = (float*)d_out;
    float* outW  = outA + (size_t)NB * NM * NH;
    float* outMW = outW + (size_t)NB * NM * NT;

    float* h1;  cudaGetSymbolAddress((void**)&h1,  g_h1);
    float* h2;  cudaGetSymbolAddress((void**)&h2,  g_h2);
    float* w1T; cudaGetSymbolAddress((void**)&w1T, g_w1T);
    float* w2T; cudaGetSymbolAddress((void**)&w2T, g_w2T);

    transpose_weights<<<2824, 256>>>(pre_w1, pre_w2, proj_w);
    mel_hist<<<dim3(NM / 256, NB), 256>>>(mel2word);
    conv_ln_relu<<<NB * (NT / 32), 256>>>(x,  x_mask, w1T, pre_b1, ln1_g, ln1_b, h1);
    conv_ln_relu<<<NB * (NT / 32), 256>>>(h1, x_mask, w2T, pre_b2, ln2_g, ln2_b, h2);
    proj_gauss  <<<NB * (NT / 16), 256>>>(x, x_mask, proj_b, gauss_w, gauss_b);
    stats_kernel<<<NB, 256>>>(x2word, outMW);
    attn_matched<<<NB * NM / 8, 256>>>(x, mel2word, outA, outW);
    attn_missing<<<dim3(NW, NB, 4), 256>>>(x, outA, outW);
}

// round 7
// speedup vs baseline: 3.7887x; 1.2157x over previous
#include <cuda_runtime.h>
#include <math.h>

#define NB 8
#define NT 512
#define NH 256
#define NM 4096
#define NW 256

typedef unsigned long long ull;

#define FMA2(d,a,b,c) asm("fma.rn.f32x2 %0,%1,%2,%3;" : "=l"(d) : "l"(a), "l"(b), "l"(c))
#define MUL2(d,a,b)   asm("mul.rn.f32x2 %0,%1,%2;"    : "=l"(d) : "l"(a), "l"(b))
#define ADD2(d,a,b)   asm("add.rn.f32x2 %0,%1,%2;"    : "=l"(d) : "l"(a), "l"(b))

__device__ __forceinline__ ull pk2(float a, float b) {
    ull d;
    asm("mov.b64 %0,{%1,%2};" : "=l"(d) : "r"(__float_as_uint(a)), "r"(__float_as_uint(b)));
    return d;
}
__device__ __forceinline__ void unpk2(ull v, float& a, float& b) {
    unsigned int l, h;
    asm("mov.b64 {%0,%1},%2;" : "=r"(l), "=r"(h) : "l"(v));
    a = __uint_as_float(l); b = __uint_as_float(h);
}

// ---------------- scratch ----------------
__device__ float g_h1[NB*NT*NH];
__device__ float g_h2[NB*NT*NH];
__device__ float g_m0[NB*NT];
__device__ float g_center[NB*NT];
__device__ int   g_phs[NB*NW];
__device__ int   g_phc[NB*NW];
__device__ int   g_mels[NB*NW];
__device__ int   g_melc[NB*NW];
__device__ int   g_cmel[NB*NW];
__device__ float g_w1T[NH*5*NH];   // [(i*5+k)*NH + o]
__device__ float g_w2T[NH*5*NH];
__device__ float g_pwT[NH*NH];     // [i*NH + o]

// ---------------- weight transpose + cmel zero ----------------
__global__ void transpose_weights(const float* __restrict__ w1,
                                  const float* __restrict__ w2,
                                  const float* __restrict__ pw)
{
    int o = threadIdx.x;
    int j = blockIdx.x;
    if (j < 1280) {
        g_w1T[j * NH + o] = w1[(size_t)o * 1280 + j];
    } else if (j < 2560) {
        int jj = j - 1280;
        g_w2T[jj * NH + o] = w2[(size_t)o * 1280 + jj];
    } else if (j < 2816) {
        int jj = j - 2560;
        g_pwT[jj * NH + o] = pw[(size_t)o * NH + jj];
    } else {
        int b = j - 2816;
        g_cmel[b * NW + o] = 0;
    }
}

// ---------------- parallel mel histogram ----------------
__global__ void mel_hist(const int* __restrict__ mel2w)
{
    int b = blockIdx.y;
    int t = blockIdx.x * 256 + threadIdx.x;
    int w = mel2w[(size_t)b * NM + t] - 1;
    atomicAdd(&g_cmel[b * NW + w], 1);
}

// ---------------- conv5 + channel-LN + relu: f32x2 over (t, t+8) pairs, TT=16 ----------------
__global__ void __launch_bounds__(256, 2) conv_ln_relu(
                             const float* __restrict__ in,
                             const float* __restrict__ mask,
                             const float* __restrict__ wT,    // [(i*5+k)*NH + o]
                             const float* __restrict__ bias,
                             const float* __restrict__ lng,
                             const float* __restrict__ lnb,
                             float* __restrict__ out)
{
    const int TT = 16;
    __shared__ ull spu[12 * NH];              // 24 KB; pair rows (x[t0+jp-2], x[t0+jp+6])
    __shared__ float mu_s[TT], rs_s[TT];

    int b  = blockIdx.x / (NT / TT);
    int t0 = (blockIdx.x % (NT / TT)) * TT;
    int o  = threadIdx.x;

    float* spf = (float*)spu;
    for (int idx = o; idx < 20 * NH; idx += 256) {
        int v = idx >> 8; int i = idx & 255;    // v -> x[t0+v-2], v = 0..19
        int t = t0 + v - 2;
        float val = 0.0f;
        if (t >= 0 && t < NT) val = in[((size_t)b * NT + t) * NH + i] * mask[b * NT + t];
        if (v < 12)  spf[(v * NH + i) * 2]           = val;   // lane0 of pair row v
        if (v >= 8)  spf[((v - 8) * NH + i) * 2 + 1] = val;   // lane1 of pair row v-8
    }
    __syncthreads();

    ull acc2[8];
    {
        float bo = bias[o];
        ull bp = pk2(bo, bo);
        #pragma unroll
        for (int j = 0; j < 8; j++) acc2[j] = bp;
    }

    const float* wp = wT + o;
    #pragma unroll 2
    for (int i = 0; i < NH; i++) {
        float w0 = wp[0], w1 = wp[NH], w2 = wp[2*NH], w3 = wp[3*NH], w4 = wp[4*NH];
        wp += 5 * NH;
        ull W0 = pk2(w0, w0), W1 = pk2(w1, w1), W2 = pk2(w2, w2), W3 = pk2(w3, w3), W4 = pk2(w4, w4);
        ull p0 = spu[i], p1 = spu[NH + i], p2 = spu[2 * NH + i], p3 = spu[3 * NH + i];
        #pragma unroll
        for (int j = 0; j < 8; j++) {
            ull p4 = spu[(j + 4) * NH + i];
            ull s;
            MUL2(s, p0, W0);
            FMA2(s, p1, W1, s);
            FMA2(s, p2, W2, s);
            FMA2(s, p3, W3, s);
            FMA2(s, p4, W4, s);
            ADD2(acc2[j], acc2[j], s);
            p0 = p1; p1 = p2; p2 = p3; p3 = p4;
        }
    }
    __syncthreads();

    float* ys = (float*)spu;                  // reuse: ys[t*NH + c], 16 KB
    #pragma unroll
    for (int j = 0; j < 8; j++) {
        float a, bb;
        unpk2(acc2[j], a, bb);
        ys[j * NH + o]       = a;             // t = j
        ys[(j + 8) * NH + o] = bb;            // t = j + 8
    }
    __syncthreads();

    int warp = o >> 5, lane = o & 31;
    for (int t = warp; t < TT; t += 8) {
        float s = 0.0f;
        for (int c = lane; c < NH; c += 32) s += ys[t * NH + c];
        for (int off = 16; off; off >>= 1) s += __shfl_xor_sync(0xffffffffu, s, off);
        float mu = s * (1.0f / NH);
        float v = 0.0f;
        for (int c = lane; c < NH; c += 32) { float d = ys[t * NH + c] - mu; v = fmaf(d, d, v); }
        for (int off = 16; off; off >>= 1) v += __shfl_xor_sync(0xffffffffu, v, off);
        v *= (1.0f / NH);
        if (lane == 0) { mu_s[t] = mu; rs_s[t] = 1.0f / sqrtf(v + 1e-4f); }
    }
    __syncthreads();

    float go = lng[o], b2 = lnb[o];
    #pragma unroll
    for (int t = 0; t < TT; t++) {
        float y = (ys[t * NH + o] - mu_s[t]) * rs_s[t] * go + b2;
        out[((size_t)b * NT + t0 + t) * NH + o] = fmaxf(y, 0.0f);
    }
}

// ---------------- proj 1x1 + residual + gauss ch0 -> m0 (R3 exact) ----------------
__global__ void __launch_bounds__(256) proj_gauss(
                           const float* __restrict__ x,
                           const float* __restrict__ mask,
                           const float* __restrict__ pb,
                           const float* __restrict__ gw,
                           const float* __restrict__ gb)
{
    const int TT = 16;
    __shared__ float hs[TT][NH];
    __shared__ float red2[256][TT + 1];

    int b  = blockIdx.x / (NT / TT);
    int t0 = (blockIdx.x % (NT / TT)) * TT;
    int o  = threadIdx.x;

    for (int idx = o; idx < TT * NH; idx += 256) {
        int tt = idx >> 8; int i = idx & 255;
        hs[tt][i] = g_h2[((size_t)b * NT + t0 + tt) * NH + i];
    }
    __syncthreads();

    float acc[TT];
    float pbo = pb[o];
    #pragma unroll
    for (int t = 0; t < TT; t++) acc[t] = pbo;

    const float* pwp = g_pwT + o;
    for (int i = 0; i < NH; i++) {
        float w = pwp[i * NH];
        #pragma unroll
        for (int t = 0; t < TT; t++) acc[t] = fmaf(w, hs[t][i], acc[t]);
    }

    float gwo = gw[o];
    #pragma unroll
    for (int t = 0; t < TT; t++) {
        float mt = mask[b * NT + t0 + t];
        float v = (x[((size_t)b * NT + t0 + t) * NH + o] + acc[t]) * mt;
        red2[o][t] = gwo * v;
    }
    __syncthreads();

    #pragma unroll
    for (int s = 128; s > 0; s >>= 1) {
        if (o < s) {
            #pragma unroll
            for (int t = 0; t < TT; t++) red2[o][t] += red2[o + s][t];
        }
        __syncthreads();
    }
    if (o < TT) {
        float g0 = red2[0][o] + gb[0];
        float mt = mask[b * NT + t0 + o];
        g_m0[b * NT + t0 + o] = (fmaxf(g0, 0.0f) + 1.0f) * mt;
    }
}

// ---------------- word stats, rescale, cumsum -> center ----------------
__global__ void stats_kernel(const int* __restrict__ x2w,
                             float* __restrict__ mword_out)
{
    int b = blockIdx.x;
    int tid = threadIdx.x;
    __shared__ int   cph[NW], sph[NW], smel[NW];
    __shared__ float sc[NW];
    __shared__ float mbuf[NT];

    if (tid < NW) cph[tid] = 0;
    __syncthreads();
    for (int p = tid; p < NT; p += 256) atomicAdd(&cph[x2w[b * NT + p] - 1], 1);
    __syncthreads();
    if (tid == 0) { int s = 0; for (int w = 0; w < NW; w++) { sph[w]  = s; s += cph[w]; } }
    if (tid == 1) { int s = 0; for (int w = 0; w < NW; w++) { smel[w] = s; s += g_cmel[b * NW + w]; } }
    __syncthreads();

    if (tid < NW) {
        int w = tid;
        int st = sph[w], c = cph[w];
        int cm = g_cmel[b * NW + w];
        float s = 0.0f;
        for (int j = 0; j < c; j++) s += g_m0[b * NT + st + j];
        mword_out[b * NW + w] = s;
        sc[w] = (float)cm / (s + 1e-4f);
        g_phs[b * NW + w] = st;      g_phc[b * NW + w] = c;
        g_mels[b * NW + w] = smel[w]; g_melc[b * NW + w] = cm;
    }
    __syncthreads();

    for (int p = tid; p < NT; p += 256) {
        int w = x2w[b * NT + p] - 1;
        float m0 = g_m0[b * NT + p];
        float d  = __fmul_rn(sc[w] - 1.0f, m0);
        mbuf[p]  = __fadd_rn(m0, d);
    }
    __syncthreads();

    if (tid == 0) {
        float c = 0.0f;
        for (int p = 0; p < NT; p++) {
            c = __fadd_rn(c, mbuf[p]);
            float half = __fmul_rn(0.5f, mbuf[p]);
            g_center[b * NT + p] = __fadd_rn(c, -half);
        }
    }
}

// ---------------- matched rows: 1 warp per mel row (float4 I/O) ----------------
__global__ void attn_matched(const float* __restrict__ x,
                             const int* __restrict__ mel2w,
                             float* __restrict__ outA,
                             float* __restrict__ outW)
{
    __shared__ float wsm[8][64];
    int warp = threadIdx.x >> 5, lane = threadIdx.x & 31;
    int row = blockIdx.x * 8 + warp;
    int b = row >> 12;
    int t = row & 4095;

    int w = mel2w[(size_t)b * NM + t] - 1;
    int cnt = g_phc[b * NW + w];
    if (cnt == 0) return;
    int lo = g_phs[b * NW + w];
    float tp = (float)t;

    float l0 = -3.4e38f, l1 = -3.4e38f;
    if (lane < cnt) {
        float d = g_center[b * NT + lo + lane] - tp;
        l0 = -(__fmul_rn(d, d)) / 10.0f;
    }
    if (lane + 32 < cnt) {
        float d = g_center[b * NT + lo + lane + 32] - tp;
        l1 = -(__fmul_rn(d, d)) / 10.0f;
    }
    float mx = fmaxf(l0, l1);
    for (int off = 16; off; off >>= 1) mx = fmaxf(mx, __shfl_xor_sync(0xffffffffu, mx, off));
    float e0 = (lane < cnt)      ? expf(l0 - mx) : 0.0f;
    float e1 = (lane + 32 < cnt) ? expf(l1 - mx) : 0.0f;
    float s = e0 + e1;
    for (int off = 16; off; off >>= 1) s += __shfl_xor_sync(0xffffffffu, s, off);
    wsm[warp][lane]      = e0 / s;
    wsm[warp][lane + 32] = e1 / s;
    __syncwarp();

    size_t wbase = ((size_t)b * NM + t) * NT;
    float4* w4 = (float4*)(outW + wbase);
    #pragma unroll
    for (int q = 0; q < 4; q++) {
        int p = q * 128 + lane * 4;
        int j0 = p - lo;
        float4 v;
        v.x = ((unsigned)(j0)     < (unsigned)cnt) ? wsm[warp][j0]     : 0.0f;
        v.y = ((unsigned)(j0 + 1) < (unsigned)cnt) ? wsm[warp][j0 + 1] : 0.0f;
        v.z = ((unsigned)(j0 + 2) < (unsigned)cnt) ? wsm[warp][j0 + 2] : 0.0f;
        v.w = ((unsigned)(j0 + 3) < (unsigned)cnt) ? wsm[warp][j0 + 3] : 0.0f;
        w4[q * 32 + lane] = v;
    }

    float4 a0 = make_float4(0.f, 0.f, 0.f, 0.f);
    float4 a1 = make_float4(0.f, 0.f, 0.f, 0.f);
    for (int j = 0; j < cnt; j++) {
        float wj = wsm[warp][j];
        const float4* xr = (const float4*)(x + ((size_t)b * NT + lo + j) * NH);
        float4 v0 = xr[lane * 2], v1 = xr[lane * 2 + 1];
        a0.x = fmaf(wj, v0.x, a0.x); a0.y = fmaf(wj, v0.y, a0.y);
        a0.z = fmaf(wj, v0.z, a0.z); a0.w = fmaf(wj, v0.w, a0.w);
        a1.x = fmaf(wj, v1.x, a1.x); a1.y = fmaf(wj, v1.y, a1.y);
        a1.z = fmaf(wj, v1.z, a1.z); a1.w = fmaf(wj, v1.w, a1.w);
    }
    float4* o4 = (float4*)(outA + ((size_t)b * NM + t) * NH);
    o4[lane * 2]     = a0;
    o4[lane * 2 + 1] = a1;
}

// ---------------- missing-word rows: chunk-split across gridDim.z ----------------
__global__ void attn_missing(const float* __restrict__ x,
                             float* __restrict__ outA,
                             float* __restrict__ outW)
{
    int w = blockIdx.x, b = blockIdx.y, z = blockIdx.z;
    if (g_phc[b * NW + w] != 0) return;
    int mc = g_melc[b * NW + w];
    if (mc == 0) return;
    int ms = g_mels[b * NW + w];

    int tid = threadIdx.x;
    int lane = tid & 31, warp = tid >> 5;
    __shared__ float wts[8][NT];
    __shared__ float cen[NT];
    __shared__ float redA[8], redB[8];

    for (int p = tid; p < NT; p += 256) cen[p] = g_center[b * NT + p];
    __syncthreads();

    for (int r0 = z * 8; r0 < mc; r0 += 32) {
        int RT = min(8, mc - r0);
        for (int r = 0; r < RT; r++) {
            float tp = (float)(ms + r0 + r);
            float d0 = cen[tid] - tp;
            float lg0 = -(__fmul_rn(d0, d0)) / 10.0f;
            float m0v = __fadd_rn(lg0, -1e9f);
            float d1 = cen[tid + 256] - tp;
            float lg1 = -(__fmul_rn(d1, d1)) / 10.0f;
            float m1v = __fadd_rn(lg1, -1e9f);

            float mx = fmaxf(m0v, m1v);
            for (int off = 16; off; off >>= 1) mx = fmaxf(mx, __shfl_xor_sync(0xffffffffu, mx, off));
            if (lane == 0) redA[warp] = mx;
            __syncthreads();
            float mall = redA[0];
            #pragma unroll
            for (int k = 1; k < 8; k++) mall = fmaxf(mall, redA[k]);

            float e0 = expf(m0v - mall);
            float e1 = expf(m1v - mall);
            float ss = e0 + e1;
            for (int off = 16; off; off >>= 1) ss += __shfl_xor_sync(0xffffffffu, ss, off);
            if (lane == 0) redB[warp] = ss;
            __syncthreads();
            float tot = redB[0];
            #pragma unroll
            for (int k = 1; k < 8; k++) tot += redB[k];

            float w0 = e0 / tot, w1 = e1 / tot;
            wts[r][tid] = w0; wts[r][tid + 256] = w1;
            size_t wb = ((size_t)b * NM + ms + r0 + r) * NT;
            outW[wb + tid] = w0; outW[wb + tid + 256] = w1;
            __syncthreads();
        }
        __syncthreads();

        float a[8];
        #pragma unroll
        for (int r = 0; r < 8; r++) a[r] = 0.0f;
        for (int p = 0; p < NT; p++) {
            float xv = x[((size_t)b * NT + p) * NH + tid];
            #pragma unroll
            for (int r = 0; r < 8; r++) a[r] = fmaf(wts[r][p], xv, a[r]);
        }
        for (int r = 0; r < RT; r++)
            outA[((size_t)b * NM + ms + r0 + r) * NH + tid] = a[r];
        __syncthreads();
    }
}

// ---------------- launcher ----------------
extern "C" void kernel_launch(void* const* d_in, const int* in_sizes, int n_in,
                              void* d_out, int out_size)
{
    const float* x       = (const float*)d_in[0];
    const float* x_mask  = (const float*)d_in[1];
    const float* pre_w1  = (const float*)d_in[2];
    const float* pre_b1  = (const float*)d_in[3];
    const float* ln1_g   = (const float*)d_in[4];
    const float* ln1_b   = (const float*)d_in[5];
    const float* pre_w2  = (const float*)d_in[6];
    const float* pre_b2  = (const float*)d_in[7];
    const float* ln2_g   = (const float*)d_in[8];
    const float* ln2_b   = (const float*)d_in[9];
    const float* proj_w  = (const float*)d_in[10];
    const float* proj_b  = (const float*)d_in[11];
    const float* gauss_w = (const float*)d_in[12];
    const float* gauss_b = (const float*)d_in[13];
    const int*   x2word  = (const int*)d_in[14];
    const int*   mel2word= (const int*)d_in[15];

    float* outA  = (float*)d_out;
    float* outW  = outA + (size_t)NB * NM * NH;
    float* outMW = outW + (size_t)NB * NM * NT;

    float* h1;  cudaGetSymbolAddress((void**)&h1,  g_h1);
    float* h2;  cudaGetSymbolAddress((void**)&h2,  g_h2);
    float* w1T; cudaGetSymbolAddress((void**)&w1T, g_w1T);
    float* w2T; cudaGetSymbolAddress((void**)&w2T, g_w2T);

    transpose_weights<<<2824, 256>>>(pre_w1, pre_w2, proj_w);
    mel_hist<<<dim3(NM / 256, NB), 256>>>(mel2word);
    conv_ln_relu<<<NB * (NT / 16), 256>>>(x,  x_mask, w1T, pre_b1, ln1_g, ln1_b, h1);
    conv_ln_relu<<<NB * (NT / 16), 256>>>(h1, x_mask, w2T, pre_b2, ln2_g, ln2_b, h2);
    proj_gauss  <<<NB * (NT / 16), 256>>>(x, x_mask, proj_b, gauss_w, gauss_b);
    stats_kernel<<<NB, 256>>>(x2word, outMW);
    attn_matched<<<NB * NM / 8, 256>>>(x, mel2word, outA, outW);
    attn_missing<<<dim3(NW, NB, 4), 256>>>(x, outA, outW);
}

// round 8
// speedup vs baseline: 4.0864x; 1.0786x over previous
#include <cuda_runtime.h>
#include <math.h>

#define NB 8
#define NT 512
#define NH 256
#define NM 4096
#define NW 256

typedef unsigned long long ull;

#define FMA2(d,a,b,c) asm("fma.rn.f32x2 %0,%1,%2,%3;" : "=l"(d) : "l"(a), "l"(b), "l"(c))
#define MUL2(d,a,b)   asm("mul.rn.f32x2 %0,%1,%2;"    : "=l"(d) : "l"(a), "l"(b))
#define ADD2(d,a,b)   asm("add.rn.f32x2 %0,%1,%2;"    : "=l"(d) : "l"(a), "l"(b))

__device__ __forceinline__ ull pk2(float a, float b) {
    ull d;
    asm("mov.b64 %0,{%1,%2};" : "=l"(d) : "r"(__float_as_uint(a)), "r"(__float_as_uint(b)));
    return d;
}
__device__ __forceinline__ void unpk2(ull v, float& a, float& b) {
    unsigned int l, h;
    asm("mov.b64 {%0,%1},%2;" : "=r"(l), "=r"(h) : "l"(v));
    a = __uint_as_float(l); b = __uint_as_float(h);
}

// ---------------- scratch ----------------
__device__ float g_h1[NB*NT*NH];
__device__ float g_h2[NB*NT*NH];
__device__ float g_m0[NB*NT];
__device__ float g_center[NB*NT];
__device__ int   g_phs[NB*NW];
__device__ int   g_phc[NB*NW];
__device__ int   g_mels[NB*NW];
__device__ int   g_melc[NB*NW];
__device__ int   g_cmel[NB*NW];
__device__ float g_w1T[NH*5*NH + 5*NH];   // [(i*5+k)*NH + o], +1 row pad for prefetch
__device__ float g_w2T[NH*5*NH + 5*NH];
__device__ float g_pwT[NH*NH];            // [i*NH + o]

// ---------------- weight transpose + cmel zero ----------------
__global__ void transpose_weights(const float* __restrict__ w1,
                                  const float* __restrict__ w2,
                                  const float* __restrict__ pw)
{
    int o = threadIdx.x;
    int j = blockIdx.x;
    if (j < 1280) {
        g_w1T[j * NH + o] = w1[(size_t)o * 1280 + j];
    } else if (j < 2560) {
        int jj = j - 1280;
        g_w2T[jj * NH + o] = w2[(size_t)o * 1280 + jj];
    } else if (j < 2816) {
        int jj = j - 2560;
        g_pwT[jj * NH + o] = pw[(size_t)o * NH + jj];
    } else {
        int b = j - 2816;
        g_cmel[b * NW + o] = 0;
    }
}

// ---------------- parallel mel histogram ----------------
__global__ void mel_hist(const int* __restrict__ mel2w)
{
    int b = blockIdx.y;
    int t = blockIdx.x * 256 + threadIdx.x;
    int w = mel2w[(size_t)b * NM + t] - 1;
    atomicAdd(&g_cmel[b * NW + w], 1);
}

// ---------------- conv5 + channel-LN + relu: f32x2 pairs, TT=16, weight prefetch ----------------
__global__ void __launch_bounds__(256, 2) conv_ln_relu(
                             const float* __restrict__ in,
                             const float* __restrict__ mask,
                             const float* __restrict__ wT,    // [(i*5+k)*NH + o], padded
                             const float* __restrict__ bias,
                             const float* __restrict__ lng,
                             const float* __restrict__ lnb,
                             float* __restrict__ out)
{
    const int TT = 16;
    __shared__ ull spu[12 * NH];              // 24 KB; pair rows
    __shared__ float mu_s[TT], rs_s[TT];

    int b  = blockIdx.x / (NT / TT);
    int t0 = (blockIdx.x % (NT / TT)) * TT;
    int o  = threadIdx.x;

    float* spf = (float*)spu;
    for (int idx = o; idx < 20 * NH; idx += 256) {
        int v = idx >> 8; int i = idx & 255;    // v -> x[t0+v-2]
        int t = t0 + v - 2;
        float val = 0.0f;
        if (t >= 0 && t < NT) val = in[((size_t)b * NT + t) * NH + i] * mask[b * NT + t];
        if (v < 12)  spf[(v * NH + i) * 2]           = val;
        if (v >= 8)  spf[((v - 8) * NH + i) * 2 + 1] = val;
    }
    __syncthreads();

    ull acc2[8];
    {
        float bo = bias[o];
        ull bp = pk2(bo, bo);
        #pragma unroll
        for (int j = 0; j < 8; j++) acc2[j] = bp;
    }

    // software-pipelined weight loads (prefetch i+1; pad row makes last load in-bounds)
    const float* wp = wT + o;
    float c0 = wp[0], c1 = wp[NH], c2 = wp[2*NH], c3 = wp[3*NH], c4 = wp[4*NH];
    #pragma unroll 2
    for (int i = 0; i < NH; i++) {
        wp += 5 * NH;
        float n0 = wp[0], n1 = wp[NH], n2 = wp[2*NH], n3 = wp[3*NH], n4 = wp[4*NH];
        ull W0 = pk2(c0, c0), W1 = pk2(c1, c1), W2 = pk2(c2, c2), W3 = pk2(c3, c3), W4 = pk2(c4, c4);
        ull p0 = spu[i], p1 = spu[NH + i], p2 = spu[2 * NH + i], p3 = spu[3 * NH + i];
        #pragma unroll
        for (int j = 0; j < 8; j++) {
            ull p4 = spu[(j + 4) * NH + i];
            ull s;
            MUL2(s, p0, W0);
            FMA2(s, p1, W1, s);
            FMA2(s, p2, W2, s);
            FMA2(s, p3, W3, s);
            FMA2(s, p4, W4, s);
            ADD2(acc2[j], acc2[j], s);
            p0 = p1; p1 = p2; p2 = p3; p3 = p4;
        }
        c0 = n0; c1 = n1; c2 = n2; c3 = n3; c4 = n4;
    }
    __syncthreads();

    float* ys = (float*)spu;
    #pragma unroll
    for (int j = 0; j < 8; j++) {
        float a, bb;
        unpk2(acc2[j], a, bb);
        ys[j * NH + o]       = a;
        ys[(j + 8) * NH + o] = bb;
    }
    __syncthreads();

    int warp = o >> 5, lane = o & 31;
    for (int t = warp; t < TT; t += 8) {
        float s = 0.0f;
        for (int c = lane; c < NH; c += 32) s += ys[t * NH + c];
        for (int off = 16; off; off >>= 1) s += __shfl_xor_sync(0xffffffffu, s, off);
        float mu = s * (1.0f / NH);
        float v = 0.0f;
        for (int c = lane; c < NH; c += 32) { float d = ys[t * NH + c] - mu; v = fmaf(d, d, v); }
        for (int off = 16; off; off >>= 1) v += __shfl_xor_sync(0xffffffffu, v, off);
        v *= (1.0f / NH);
        if (lane == 0) { mu_s[t] = mu; rs_s[t] = 1.0f / sqrtf(v + 1e-4f); }
    }
    __syncthreads();

    float go = lng[o], b2 = lnb[o];
    #pragma unroll
    for (int t = 0; t < TT; t++) {
        float y = (ys[t * NH + o] - mu_s[t]) * rs_s[t] * go + b2;
        out[((size_t)b * NT + t0 + t) * NH + o] = fmaxf(y, 0.0f);
    }
}

// ---------------- proj 1x1 + residual + gauss ch0 -> m0 (R3 exact) ----------------
__global__ void __launch_bounds__(256) proj_gauss(
                           const float* __restrict__ x,
                           const float* __restrict__ mask,
                           const float* __restrict__ pb,
                           const float* __restrict__ gw,
                           const float* __restrict__ gb)
{
    const int TT = 16;
    __shared__ float hs[TT][NH];
    __shared__ float red2[256][TT + 1];

    int b  = blockIdx.x / (NT / TT);
    int t0 = (blockIdx.x % (NT / TT)) * TT;
    int o  = threadIdx.x;

    for (int idx = o; idx < TT * NH; idx += 256) {
        int tt = idx >> 8; int i = idx & 255;
        hs[tt][i] = g_h2[((size_t)b * NT + t0 + tt) * NH + i];
    }
    __syncthreads();

    float acc[TT];
    float pbo = pb[o];
    #pragma unroll
    for (int t = 0; t < TT; t++) acc[t] = pbo;

    const float* pwp = g_pwT + o;
    for (int i = 0; i < NH; i++) {
        float w = pwp[i * NH];
        #pragma unroll
        for (int t = 0; t < TT; t++) acc[t] = fmaf(w, hs[t][i], acc[t]);
    }

    float gwo = gw[o];
    #pragma unroll
    for (int t = 0; t < TT; t++) {
        float mt = mask[b * NT + t0 + t];
        float v = (x[((size_t)b * NT + t0 + t) * NH + o] + acc[t]) * mt;
        red2[o][t] = gwo * v;
    }
    __syncthreads();

    #pragma unroll
    for (int s = 128; s > 0; s >>= 1) {
        if (o < s) {
            #pragma unroll
            for (int t = 0; t < TT; t++) red2[o][t] += red2[o + s][t];
        }
        __syncthreads();
    }
    if (o < TT) {
        float g0 = red2[0][o] + gb[0];
        float mt = mask[b * NT + t0 + o];
        g_m0[b * NT + t0 + o] = (fmaxf(g0, 0.0f) + 1.0f) * mt;
    }
}

// ---------------- word stats, rescale, cumsum -> center ----------------
__global__ void stats_kernel(const int* __restrict__ x2w,
                             float* __restrict__ mword_out)
{
    int b = blockIdx.x;
    int tid = threadIdx.x;
    __shared__ int   cph[NW], sph[NW], smel[NW];
    __shared__ float sc[NW];
    __shared__ float mbuf[NT];

    if (tid < NW) cph[tid] = 0;
    __syncthreads();
    for (int p = tid; p < NT; p += 256) atomicAdd(&cph[x2w[b * NT + p] - 1], 1);
    __syncthreads();
    if (tid == 0) { int s = 0; for (int w = 0; w < NW; w++) { sph[w]  = s; s += cph[w]; } }
    if (tid == 1) { int s = 0; for (int w = 0; w < NW; w++) { smel[w] = s; s += g_cmel[b * NW + w]; } }
    __syncthreads();

    if (tid < NW) {
        int w = tid;
        int st = sph[w], c = cph[w];
        int cm = g_cmel[b * NW + w];
        float s = 0.0f;
        for (int j = 0; j < c; j++) s += g_m0[b * NT + st + j];
        mword_out[b * NW + w] = s;
        sc[w] = (float)cm / (s + 1e-4f);
        g_phs[b * NW + w] = st;      g_phc[b * NW + w] = c;
        g_mels[b * NW + w] = smel[w]; g_melc[b * NW + w] = cm;
    }
    __syncthreads();

    for (int p = tid; p < NT; p += 256) {
        int w = x2w[b * NT + p] - 1;
        float m0 = g_m0[b * NT + p];
        float d  = __fmul_rn(sc[w] - 1.0f, m0);
        mbuf[p]  = __fadd_rn(m0, d);
    }
    __syncthreads();

    if (tid == 0) {
        float c = 0.0f;
        for (int p = 0; p < NT; p++) {
            c = __fadd_rn(c, mbuf[p]);
            float half = __fmul_rn(0.5f, mbuf[p]);
            g_center[b * NT + p] = __fadd_rn(c, -half);
        }
    }
}

// ---------------- fused attention: missing-word blocks FIRST, then matched rows ----------------
#define MISS_BLKS (NW * NB * 4)     // 8192
__global__ void __launch_bounds__(256) attn_fused(
                             const float* __restrict__ x,
                             const int* __restrict__ mel2w,
                             float* __restrict__ outA,
                             float* __restrict__ outW)
{
    __shared__ float wsm[8][64];
    __shared__ float wts[8][NT];
    __shared__ float cen[NT];
    __shared__ float redA[8], redB[8];

    if (blockIdx.x < MISS_BLKS) {
        // ---- missing-word path (long-running, scheduled first) ----
        int idx = blockIdx.x;
        int w = idx & 255;
        int b = (idx >> 8) & 7;
        int z = idx >> 11;               // 0..3
        if (g_phc[b * NW + w] != 0) return;
        int mc = g_melc[b * NW + w];
        if (mc == 0) return;
        int ms = g_mels[b * NW + w];

        int tid = threadIdx.x;
        int lane = tid & 31, warp = tid >> 5;

        for (int p = tid; p < NT; p += 256) cen[p] = g_center[b * NT + p];
        __syncthreads();

        for (int r0 = z * 8; r0 < mc; r0 += 32) {
            int RT = min(8, mc - r0);
            for (int r = 0; r < RT; r++) {
                float tp = (float)(ms + r0 + r);
                float d0 = cen[tid] - tp;
                float lg0 = -(__fmul_rn(d0, d0)) / 10.0f;
                float m0v = __fadd_rn(lg0, -1e9f);
                float d1 = cen[tid + 256] - tp;
                float lg1 = -(__fmul_rn(d1, d1)) / 10.0f;
                float m1v = __fadd_rn(lg1, -1e9f);

                float mx = fmaxf(m0v, m1v);
                for (int off = 16; off; off >>= 1) mx = fmaxf(mx, __shfl_xor_sync(0xffffffffu, mx, off));
                if (lane == 0) redA[warp] = mx;
                __syncthreads();
                float mall = redA[0];
                #pragma unroll
                for (int k = 1; k < 8; k++) mall = fmaxf(mall, redA[k]);

                float e0 = expf(m0v - mall);
                float e1 = expf(m1v - mall);
                float ss = e0 + e1;
                for (int off = 16; off; off >>= 1) ss += __shfl_xor_sync(0xffffffffu, ss, off);
                if (lane == 0) redB[warp] = ss;
                __syncthreads();
                float tot = redB[0];
                #pragma unroll
                for (int k = 1; k < 8; k++) tot += redB[k];

                float w0 = e0 / tot, w1 = e1 / tot;
                wts[r][tid] = w0; wts[r][tid + 256] = w1;
                size_t wb = ((size_t)b * NM + ms + r0 + r) * NT;
                outW[wb + tid] = w0; outW[wb + tid + 256] = w1;
                __syncthreads();
            }
            __syncthreads();

            float a[8];
            #pragma unroll
            for (int r = 0; r < 8; r++) a[r] = 0.0f;
            for (int p = 0; p < NT; p++) {
                float xv = x[((size_t)b * NT + p) * NH + tid];
                #pragma unroll
                for (int r = 0; r < 8; r++) a[r] = fmaf(wts[r][p], xv, a[r]);
            }
            for (int r = 0; r < RT; r++)
                outA[((size_t)b * NM + ms + r0 + r) * NH + tid] = a[r];
            __syncthreads();
        }
    } else {
        // ---- matched path: one warp per mel row ----
        int warp = threadIdx.x >> 5, lane = threadIdx.x & 31;
        int row = (blockIdx.x - MISS_BLKS) * 8 + warp;
        int b = row >> 12;
        int t = row & 4095;

        int w = mel2w[(size_t)b * NM + t] - 1;
        int cnt = g_phc[b * NW + w];
        if (cnt == 0) return;
        int lo = g_phs[b * NW + w];
        float tp = (float)t;

        float l0 = -3.4e38f, l1 = -3.4e38f;
        if (lane < cnt) {
            float d = g_center[b * NT + lo + lane] - tp;
            l0 = -(__fmul_rn(d, d)) / 10.0f;
        }
        if (lane + 32 < cnt) {
            float d = g_center[b * NT + lo + lane + 32] - tp;
            l1 = -(__fmul_rn(d, d)) / 10.0f;
        }
        float mx = fmaxf(l0, l1);
        for (int off = 16; off; off >>= 1) mx = fmaxf(mx, __shfl_xor_sync(0xffffffffu, mx, off));
        float e0 = (lane < cnt)      ? expf(l0 - mx) : 0.0f;
        float e1 = (lane + 32 < cnt) ? expf(l1 - mx) : 0.0f;
        float s = e0 + e1;
        for (int off = 16; off; off >>= 1) s += __shfl_xor_sync(0xffffffffu, s, off);
        wsm[warp][lane]      = e0 / s;
        wsm[warp][lane + 32] = e1 / s;
        __syncwarp();

        size_t wbase = ((size_t)b * NM + t) * NT;
        float4* w4 = (float4*)(outW + wbase);
        #pragma unroll
        for (int q = 0; q < 4; q++) {
            int p = q * 128 + lane * 4;
            int j0 = p - lo;
            float4 v;
            v.x = ((unsigned)(j0)     < (unsigned)cnt) ? wsm[warp][j0]     : 0.0f;
            v.y = ((unsigned)(j0 + 1) < (unsigned)cnt) ? wsm[warp][j0 + 1] : 0.0f;
            v.z = ((unsigned)(j0 + 2) < (unsigned)cnt) ? wsm[warp][j0 + 2] : 0.0f;
            v.w = ((unsigned)(j0 + 3) < (unsigned)cnt) ? wsm[warp][j0 + 3] : 0.0f;
            w4[q * 32 + lane] = v;
        }

        float4 a0 = make_float4(0.f, 0.f, 0.f, 0.f);
        float4 a1 = make_float4(0.f, 0.f, 0.f, 0.f);
        for (int j = 0; j < cnt; j++) {
            float wj = wsm[warp][j];
            const float4* xr = (const float4*)(x + ((size_t)b * NT + lo + j) * NH);
            float4 v0 = xr[lane * 2], v1 = xr[lane * 2 + 1];
            a0.x = fmaf(wj, v0.x, a0.x); a0.y = fmaf(wj, v0.y, a0.y);
            a0.z = fmaf(wj, v0.z, a0.z); a0.w = fmaf(wj, v0.w, a0.w);
            a1.x = fmaf(wj, v1.x, a1.x); a1.y = fmaf(wj, v1.y, a1.y);
            a1.z = fmaf(wj, v1.z, a1.z); a1.w = fmaf(wj, v1.w, a1.w);
        }
        float4* o4 = (float4*)(outA + ((size_t)b * NM + t) * NH);
        o4[lane * 2]     = a0;
        o4[lane * 2 + 1] = a1;
    }
}

// ---------------- launcher ----------------
extern "C" void kernel_launch(void* const* d_in, const int* in_sizes, int n_in,
                              void* d_out, int out_size)
{
    const float* x       = (const float*)d_in[0];
    const float* x_mask  = (const float*)d_in[1];
    const float* pre_w1  = (const float*)d_in[2];
    const float* pre_b1  = (const float*)d_in[3];
    const float* ln1_g   = (const float*)d_in[4];
    const float* ln1_b   = (const float*)d_in[5];
    const float* pre_w2  = (const float*)d_in[6];
    const float* pre_b2  = (const float*)d_in[7];
    const float* ln2_g   = (const float*)d_in[8];
    const float* ln2_b   = (const float*)d_in[9];
    const float* proj_w  = (const float*)d_in[10];
    const float* proj_b  = (const float*)d_in[11];
    const float* gauss_w = (const float*)d_in[12];
    const float* gauss_b = (const float*)d_in[13];
    const int*   x2word  = (const int*)d_in[14];
    const int*   mel2word= (const int*)d_in[15];

    float* outA  = (float*)d_out;
    float* outW  = outA + (size_t)NB * NM * NH;
    float* outMW = outW + (size_t)NB * NM * NT;

    float* h1;  cudaGetSymbolAddress((void**)&h1,  g_h1);
    float* h2;  cudaGetSymbolAddress((void**)&h2,  g_h2);
    float* w1T; cudaGetSymbolAddress((void**)&w1T, g_w1T);
    float* w2T; cudaGetSymbolAddress((void**)&w2T, g_w2T);

    transpose_weights<<<2824, 256>>>(pre_w1, pre_w2, proj_w);
    mel_hist<<<dim3(NM / 256, NB), 256>>>(mel2word);
    conv_ln_relu<<<NB * (NT / 16), 256>>>(x,  x_mask, w1T, pre_b1, ln1_g, ln1_b, h1);
    conv_ln_relu<<<NB * (NT / 16), 256>>>(h1, x_mask, w2T, pre_b2, ln2_g, ln2_b, h2);
    proj_gauss  <<<NB * (NT / 16), 256>>>(x, x_mask, proj_b, gauss_w, gauss_b);
    stats_kernel<<<NB, 256>>>(x2word, outMW);
    attn_fused  <<<MISS_BLKS + NB * NM / 8, 256>>>(x, mel2word, outA, outW);
}